// round 2
// baseline (speedup 1.0000x reference)
#include <cuda_runtime.h>
#include <cstdint>
#include <cstddef>

#define BATCH 8
#define SEQ   2048
#define HID   256
#define INDIM 96

// ---------------- scratch ----------------
__device__ float g_q[BATCH * SEQ * HID];
__device__ float g_k[BATCH * SEQ * HID];
__device__ float g_v[BATCH * SEQ * HID];

// ---------------- helpers ----------------
__device__ __forceinline__ unsigned f2tf32(float x) {
    unsigned r;
    asm("cvt.rna.tf32.f32 %0, %1;" : "=r"(r) : "f"(x));
    return r;
}
__device__ __forceinline__ float tf32f(float x) {
    return __uint_as_float(f2tf32(x));
}
__device__ __forceinline__ void split_tf32(float x, float& hi, float& lo) {
    hi = __uint_as_float(f2tf32(x));
    lo = __uint_as_float(f2tf32(x - hi));
}
__device__ __forceinline__ void mma_tf32(float c[4], const unsigned a[4], const unsigned b[2]) {
    asm("mma.sync.aligned.m16n8k8.row.col.f32.tf32.tf32.f32 "
        "{%0,%1,%2,%3}, {%4,%5,%6,%7}, {%8,%9}, {%0,%1,%2,%3};\n"
        : "+f"(c[0]), "+f"(c[1]), "+f"(c[2]), "+f"(c[3])
        : "r"(a[0]), "r"(a[1]), "r"(a[2]), "r"(a[3]), "r"(b[0]), "r"(b[1]));
}

// ================= kernel 1: projections via 3xTF32 MMA =================
// grid (128 rowtiles, 2 coltiles, 3 projs), block 256 (8 warps, 4m x 2n).
// Tile 128x128, K=96 in chunks of 16. acc in fp32; hh+hl+lh splits -> fp32 accuracy.
__global__ void __launch_bounds__(256) proj_kernel(
    const float* __restrict__ xq, const float* __restrict__ xk, const float* __restrict__ xv,
    const float* __restrict__ Wq, const float* __restrict__ bq,
    const float* __restrict__ Wk, const float* __restrict__ bk,
    const float* __restrict__ Wv, const float* __restrict__ bv)
{
    const int proj = blockIdx.z;
    const float* x; const float* W; const float* bias; float* o;
    if (proj == 0)      { x = xq; W = Wq; bias = bq; o = g_q; }
    else if (proj == 1) { x = xk; W = Wk; bias = bk; o = g_k; }
    else                { x = xv; W = Wv; bias = bv; o = g_v; }

    const int row0 = blockIdx.x * 128;
    const int h0   = blockIdx.y * 128;

    __shared__ float xs_hi[128 * 20], xs_lo[128 * 20];   // [r][k] stride 20
    __shared__ float ws_hi[128 * 17], ws_lo[128 * 17];   // [n][k] stride 17

    const int tid = threadIdx.x;
    const int warp = tid >> 5, lane = tid & 31;
    const int wm = warp & 3, wn = warp >> 2;
    const int tg = lane & 3, gi = lane >> 2;

    float acc[2][8][4];
#pragma unroll
    for (int mi = 0; mi < 2; mi++)
#pragma unroll
        for (int ni = 0; ni < 8; ni++)
#pragma unroll
            for (int c = 0; c < 4; c++) acc[mi][ni][c] = 0.f;

    for (int kc = 0; kc < INDIM; kc += 16) {
        // x tile: 128 rows x 16 cols
#pragma unroll
        for (int i = 0; i < 2; i++) {
            int f4 = tid + i * 256;              // 0..511
            int r = f4 >> 2, c4 = (f4 & 3) * 4;
            float4 xv4 = *(const float4*)(x + (size_t)(row0 + r) * INDIM + kc + c4);
            float h0f, l0, h1, l1, h2, l2, h3, l3;
            split_tf32(xv4.x, h0f, l0); split_tf32(xv4.y, h1, l1);
            split_tf32(xv4.z, h2, l2); split_tf32(xv4.w, h3, l3);
            float* dh = xs_hi + r * 20 + c4;
            float* dl = xs_lo + r * 20 + c4;
            dh[0] = h0f; dh[1] = h1; dh[2] = h2; dh[3] = h3;
            dl[0] = l0;  dl[1] = l1; dl[2] = l2; dl[3] = l3;
        }
        // W tile: 16 k-rows x 128 cols, transposed into [n][k]
#pragma unroll
        for (int i = 0; i < 2; i++) {
            int f4 = tid + i * 256;              // 0..511
            int k = f4 >> 5, n4 = (f4 & 31) * 4;
            float4 wv4 = *(const float4*)(W + (size_t)(kc + k) * HID + h0 + n4);
            float h0f, l0, h1, l1, h2, l2, h3, l3;
            split_tf32(wv4.x, h0f, l0); split_tf32(wv4.y, h1, l1);
            split_tf32(wv4.z, h2, l2); split_tf32(wv4.w, h3, l3);
            ws_hi[(n4 + 0) * 17 + k] = h0f; ws_lo[(n4 + 0) * 17 + k] = l0;
            ws_hi[(n4 + 1) * 17 + k] = h1;  ws_lo[(n4 + 1) * 17 + k] = l1;
            ws_hi[(n4 + 2) * 17 + k] = h2;  ws_lo[(n4 + 2) * 17 + k] = l2;
            ws_hi[(n4 + 3) * 17 + k] = h3;  ws_lo[(n4 + 3) * 17 + k] = l3;
        }
        __syncthreads();
#pragma unroll
        for (int ks = 0; ks < 16; ks += 8) {
            unsigned ah[2][4], al[2][4], bh[8][2], bl[8][2];
#pragma unroll
            for (int mi = 0; mi < 2; mi++) {
                int r = wm * 32 + mi * 16 + gi;
                ah[mi][0] = __float_as_uint(xs_hi[r * 20 + ks + tg]);
                ah[mi][1] = __float_as_uint(xs_hi[(r + 8) * 20 + ks + tg]);
                ah[mi][2] = __float_as_uint(xs_hi[r * 20 + ks + tg + 4]);
                ah[mi][3] = __float_as_uint(xs_hi[(r + 8) * 20 + ks + tg + 4]);
                al[mi][0] = __float_as_uint(xs_lo[r * 20 + ks + tg]);
                al[mi][1] = __float_as_uint(xs_lo[(r + 8) * 20 + ks + tg]);
                al[mi][2] = __float_as_uint(xs_lo[r * 20 + ks + tg + 4]);
                al[mi][3] = __float_as_uint(xs_lo[(r + 8) * 20 + ks + tg + 4]);
            }
#pragma unroll
            for (int ni = 0; ni < 8; ni++) {
                int n = wn * 64 + ni * 8 + gi;
                bh[ni][0] = __float_as_uint(ws_hi[n * 17 + ks + tg]);
                bh[ni][1] = __float_as_uint(ws_hi[n * 17 + ks + tg + 4]);
                bl[ni][0] = __float_as_uint(ws_lo[n * 17 + ks + tg]);
                bl[ni][1] = __float_as_uint(ws_lo[n * 17 + ks + tg + 4]);
            }
#pragma unroll
            for (int mi = 0; mi < 2; mi++)
#pragma unroll
                for (int ni = 0; ni < 8; ni++) {
                    mma_tf32(acc[mi][ni], ah[mi], bh[ni]);
                    mma_tf32(acc[mi][ni], ah[mi], bl[ni]);
                    mma_tf32(acc[mi][ni], al[mi], bh[ni]);
                }
        }
        __syncthreads();
    }
    // epilogue: + bias
#pragma unroll
    for (int mi = 0; mi < 2; mi++) {
        int r0 = row0 + wm * 32 + mi * 16 + gi;
        int r1 = r0 + 8;
#pragma unroll
        for (int ni = 0; ni < 8; ni++) {
            int c = h0 + wn * 64 + ni * 8 + tg * 2;
            float2 bb = *(const float2*)(bias + c);
            *(float2*)(o + (size_t)r0 * HID + c) = make_float2(acc[mi][ni][0] + bb.x, acc[mi][ni][1] + bb.y);
            *(float2*)(o + (size_t)r1 * HID + c) = make_float2(acc[mi][ni][2] + bb.x, acc[mi][ni][3] + bb.y);
        }
    }
}

// ================= kernel 2: fused flash attention + LayerNorm =================
// grid (16 qtiles, 8 batches), block 512 (16 warps, 4m x 4n).
// Per block: Q tile 128 rows (smem, tf32). Loop over 32 key-tiles of 64:
//   S = Q K^T (tf32 MMA) -> exp(masked) -> P to smem -> O += P V (tf32 MMA).
// Rowsums in regs. Final: normalize + LayerNorm + write.
#define QT 128
#define KT 64
#define QS_STRIDE 260
#define KS_STRIDE 132
#define PS_STRIDE 68
#define VS_STRIDE 68
#define ATTN_SMEM_FLOATS (QT*QS_STRIDE + KT*KS_STRIDE + QT*PS_STRIDE + KT*VS_STRIDE + 4*QT*2)
#define ATTN_SMEM_BYTES  (ATTN_SMEM_FLOATS * 4)

__global__ void __launch_bounds__(512) attn_kernel(const int* __restrict__ mask,
                                                   const float* __restrict__ gamma,
                                                   const float* __restrict__ beta,
                                                   float* __restrict__ out)
{
    const int qt = blockIdx.x, b = blockIdx.y;
    extern __shared__ float sm[];
    float* Qs    = sm;                        // 128 x 260
    float* Ks    = Qs + QT * QS_STRIDE;       // 64 x 132
    float* Ps    = Ks + KT * KS_STRIDE;       // 128 x 68  (also mask staging)
    float* Vs    = Ps + QT * PS_STRIDE;       // 64 x 68
    float* rstat = Vs + KT * VS_STRIDE;       // 4 x 128 x 2

    const int tid = threadIdx.x;
    const int warp = tid >> 5, lane = tid & 31;
    const int wm = warp & 3, wn = warp >> 2;
    const int tg = lane & 3, gi = lane >> 2;

    const float* Qg = g_q + ((size_t)b * SEQ + qt * QT) * HID;
    const float* Kg = g_k + (size_t)b * SEQ * HID;
    const float* Vg = g_v + (size_t)b * SEQ * HID;
    const int* Mg = mask + ((size_t)b * SEQ + qt * QT) * SEQ;

    // load Q tile as tf32
#pragma unroll
    for (int i = 0; i < 16; i++) {
        int f4 = tid + i * 512;                  // 0..8191
        int r = f4 >> 6, c4 = (f4 & 63) * 4;
        float4 qv = *(const float4*)(Qg + (size_t)r * HID + c4);
        float* d = Qs + r * QS_STRIDE + c4;
        d[0] = tf32f(qv.x); d[1] = tf32f(qv.y); d[2] = tf32f(qv.z); d[3] = tf32f(qv.w);
    }

    float accO[2][8][4];
#pragma unroll
    for (int mi = 0; mi < 2; mi++)
#pragma unroll
        for (int ni = 0; ni < 8; ni++)
#pragma unroll
            for (int c = 0; c < 4; c++) accO[mi][ni][c] = 0.f;
    float rs[2][2] = {{0.f, 0.f}, {0.f, 0.f}};

    __syncthreads();

    for (int kt = 0; kt < SEQ / KT; kt++) {
        // --- stage mask tile into Ps (int bits), one-to-one with P layout ---
#pragma unroll
        for (int i = 0; i < 4; i++) {
            int f4 = tid + i * 512;              // 0..2047 (128 rows x 16 int4)
            int r = f4 >> 4, c4 = (f4 & 15) * 4;
            int4 mv = *(const int4*)(Mg + (size_t)r * SEQ + kt * KT + c4);
            float* d = Ps + r * PS_STRIDE + c4;
            d[0] = __int_as_float(mv.x); d[1] = __int_as_float(mv.y);
            d[2] = __int_as_float(mv.z); d[3] = __int_as_float(mv.w);
        }

        // --- S = Q K^T over HID=256, kc chunks of 128 ---
        float accS[2][2][4];
#pragma unroll
        for (int mi = 0; mi < 2; mi++)
#pragma unroll
            for (int ni = 0; ni < 2; ni++)
#pragma unroll
                for (int c = 0; c < 4; c++) accS[mi][ni][c] = 0.f;

        for (int kc = 0; kc < HID; kc += 128) {
#pragma unroll
            for (int i = 0; i < 4; i++) {
                int f4 = tid + i * 512;          // 0..2047 (64 rows x 32 float4)
                int r = f4 >> 5, c4 = (f4 & 31) * 4;
                float4 kv = *(const float4*)(Kg + (size_t)(kt * KT + r) * HID + kc + c4);
                float* d = Ks + r * KS_STRIDE + c4;
                d[0] = tf32f(kv.x); d[1] = tf32f(kv.y); d[2] = tf32f(kv.z); d[3] = tf32f(kv.w);
            }
            __syncthreads();
#pragma unroll
            for (int ks = 0; ks < 128; ks += 8) {
                unsigned a[2][4], bb[2][2];
#pragma unroll
                for (int mi = 0; mi < 2; mi++) {
                    int r = wm * 32 + mi * 16 + gi;
                    const float* q0 = Qs + r * QS_STRIDE + kc + ks + tg;
                    a[mi][0] = __float_as_uint(q0[0]);
                    a[mi][1] = __float_as_uint(q0[8 * QS_STRIDE]);
                    a[mi][2] = __float_as_uint(q0[4]);
                    a[mi][3] = __float_as_uint(q0[8 * QS_STRIDE + 4]);
                }
#pragma unroll
                for (int ni = 0; ni < 2; ni++) {
                    int n = wn * 16 + ni * 8 + gi;
                    bb[ni][0] = __float_as_uint(Ks[n * KS_STRIDE + ks + tg]);
                    bb[ni][1] = __float_as_uint(Ks[n * KS_STRIDE + ks + tg + 4]);
                }
#pragma unroll
                for (int mi = 0; mi < 2; mi++)
#pragma unroll
                    for (int ni = 0; ni < 2; ni++)
                        mma_tf32(accS[mi][ni], a[mi], bb[ni]);
            }
            __syncthreads();
        }

        // --- epilogue: mask (from Ps), exp, rowsum, write P (tf32) into Ps ---
        const float scale = 0.0625f;
#pragma unroll
        for (int mi = 0; mi < 2; mi++) {
            int r0 = wm * 32 + mi * 16 + gi;
            int r1 = r0 + 8;
#pragma unroll
            for (int ni = 0; ni < 2; ni++) {
                int c = wn * 16 + ni * 8 + tg * 2;
                float* p0 = Ps + r0 * PS_STRIDE + c;
                float* p1 = Ps + r1 * PS_STRIDE + c;
                int m00 = __float_as_int(p0[0]), m01 = __float_as_int(p0[1]);
                int m10 = __float_as_int(p1[0]), m11 = __float_as_int(p1[1]);
                float p00 = m00 ? __expf(accS[mi][ni][0] * scale) : 0.f;
                float p01 = m01 ? __expf(accS[mi][ni][1] * scale) : 0.f;
                float p10 = m10 ? __expf(accS[mi][ni][2] * scale) : 0.f;
                float p11 = m11 ? __expf(accS[mi][ni][3] * scale) : 0.f;
                rs[mi][0] += p00 + p01;
                rs[mi][1] += p10 + p11;
                p0[0] = tf32f(p00); p0[1] = tf32f(p01);
                p1[0] = tf32f(p10); p1[1] = tf32f(p11);
            }
        }
        __syncthreads();

        // --- O += P V, V in 4 column chunks of 64 ---
#pragma unroll
        for (int vc = 0; vc < 4; vc++) {
#pragma unroll
            for (int i = 0; i < 2; i++) {
                int f4 = tid + i * 512;          // 0..1023 (64 rows x 16 float4)
                int r = f4 >> 4, c4 = (f4 & 15) * 4;
                float4 vv = *(const float4*)(Vg + (size_t)(kt * KT + r) * HID + vc * 64 + c4);
                float* d = Vs + r * VS_STRIDE + c4;
                d[0] = tf32f(vv.x); d[1] = tf32f(vv.y); d[2] = tf32f(vv.z); d[3] = tf32f(vv.w);
            }
            __syncthreads();
#pragma unroll
            for (int ks = 0; ks < KT; ks += 8) {
                unsigned a[2][4], bb[2][2];
#pragma unroll
                for (int mi = 0; mi < 2; mi++) {
                    int r = wm * 32 + mi * 16 + gi;
                    const float* p0 = Ps + r * PS_STRIDE + ks + tg;
                    a[mi][0] = __float_as_uint(p0[0]);
                    a[mi][1] = __float_as_uint(p0[8 * PS_STRIDE]);
                    a[mi][2] = __float_as_uint(p0[4]);
                    a[mi][3] = __float_as_uint(p0[8 * PS_STRIDE + 4]);
                }
#pragma unroll
                for (int nf = 0; nf < 2; nf++) {
                    int n = wn * 16 + nf * 8 + gi;
                    bb[nf][0] = __float_as_uint(Vs[(ks + tg) * VS_STRIDE + n]);
                    bb[nf][1] = __float_as_uint(Vs[(ks + tg + 4) * VS_STRIDE + n]);
                }
#pragma unroll
                for (int mi = 0; mi < 2; mi++)
#pragma unroll
                    for (int nf = 0; nf < 2; nf++)
                        mma_tf32(accO[mi][vc * 2 + nf], a[mi], bb[nf]);
            }
            __syncthreads();
        }
    }

    // ---- rowsum reduction ----
#pragma unroll
    for (int mi = 0; mi < 2; mi++) {
#pragma unroll
        for (int rr = 0; rr < 2; rr++) {
            float v = rs[mi][rr];
            v += __shfl_xor_sync(0xffffffffu, v, 1);
            v += __shfl_xor_sync(0xffffffffu, v, 2);
            rs[mi][rr] = v;
        }
        if (tg == 0) {
            int rl = wm * 32 + mi * 16 + gi;
            rstat[wn * 256 + rl * 2]       = rs[mi][0];
            rstat[wn * 256 + (rl + 8) * 2] = rs[mi][1];
        }
    }
    __syncthreads();

    float inv[2][2];
#pragma unroll
    for (int mi = 0; mi < 2; mi++) {
        int rl0 = wm * 32 + mi * 16 + gi;
        int rl1 = rl0 + 8;
        float t0 = rstat[rl0 * 2] + rstat[256 + rl0 * 2] + rstat[512 + rl0 * 2] + rstat[768 + rl0 * 2];
        float t1 = rstat[rl1 * 2] + rstat[256 + rl1 * 2] + rstat[512 + rl1 * 2] + rstat[768 + rl1 * 2];
        inv[mi][0] = 1.f / t0;
        inv[mi][1] = 1.f / t1;
    }
    __syncthreads();

    // ---- normalize + per-row sum/sumsq ----
#pragma unroll
    for (int mi = 0; mi < 2; mi++) {
        float s0 = 0.f, s1 = 0.f, q0 = 0.f, q1 = 0.f;
#pragma unroll
        for (int ni = 0; ni < 8; ni++) {
            float v00 = accO[mi][ni][0] * inv[mi][0]; accO[mi][ni][0] = v00;
            float v01 = accO[mi][ni][1] * inv[mi][0]; accO[mi][ni][1] = v01;
            float v10 = accO[mi][ni][2] * inv[mi][1]; accO[mi][ni][2] = v10;
            float v11 = accO[mi][ni][3] * inv[mi][1]; accO[mi][ni][3] = v11;
            s0 += v00 + v01; s1 += v10 + v11;
            q0 += v00 * v00 + v01 * v01;
            q1 += v10 * v10 + v11 * v11;
        }
        s0 += __shfl_xor_sync(0xffffffffu, s0, 1); s0 += __shfl_xor_sync(0xffffffffu, s0, 2);
        s1 += __shfl_xor_sync(0xffffffffu, s1, 1); s1 += __shfl_xor_sync(0xffffffffu, s1, 2);
        q0 += __shfl_xor_sync(0xffffffffu, q0, 1); q0 += __shfl_xor_sync(0xffffffffu, q0, 2);
        q1 += __shfl_xor_sync(0xffffffffu, q1, 1); q1 += __shfl_xor_sync(0xffffffffu, q1, 2);
        if (tg == 0) {
            int rl0 = wm * 32 + mi * 16 + gi;
            int rl1 = rl0 + 8;
            rstat[wn * 256 + rl0 * 2]     = s0;
            rstat[wn * 256 + rl0 * 2 + 1] = q0;
            rstat[wn * 256 + rl1 * 2]     = s1;
            rstat[wn * 256 + rl1 * 2 + 1] = q1;
        }
    }
    __syncthreads();

    // ---- LayerNorm + write out ----
#pragma unroll
    for (int mi = 0; mi < 2; mi++) {
        int rl0 = wm * 32 + mi * 16 + gi;
        int rl1 = rl0 + 8;
        float sum0 = rstat[rl0*2] + rstat[256 + rl0*2] + rstat[512 + rl0*2] + rstat[768 + rl0*2];
        float sq0  = rstat[rl0*2+1] + rstat[256 + rl0*2+1] + rstat[512 + rl0*2+1] + rstat[768 + rl0*2+1];
        float sum1 = rstat[rl1*2] + rstat[256 + rl1*2] + rstat[512 + rl1*2] + rstat[768 + rl1*2];
        float sq1  = rstat[rl1*2+1] + rstat[256 + rl1*2+1] + rstat[512 + rl1*2+1] + rstat[768 + rl1*2+1];
        float mu0 = sum0 * (1.f / HID);
        float mu1 = sum1 * (1.f / HID);
        float var0 = sq0 * (1.f / HID) - mu0 * mu0;
        float var1 = sq1 * (1.f / HID) - mu1 * mu1;
        float rstd0 = rsqrtf(var0 + 1e-6f);
        float rstd1 = rsqrtf(var1 + 1e-6f);
        size_t orow0 = ((size_t)b * SEQ + qt * QT + rl0) * HID;
        size_t orow1 = ((size_t)b * SEQ + qt * QT + rl1) * HID;
#pragma unroll
        for (int ni = 0; ni < 8; ni++) {
            int vc = ni >> 1, nf = ni & 1;
            int c = vc * 64 + wn * 16 + nf * 8 + tg * 2;
            float2 gm = *(const float2*)(gamma + c);
            float2 bt = *(const float2*)(beta + c);
            float2 o0, o1;
            o0.x = (accO[mi][ni][0] - mu0) * rstd0 * gm.x + bt.x;
            o0.y = (accO[mi][ni][1] - mu0) * rstd0 * gm.y + bt.y;
            o1.x = (accO[mi][ni][2] - mu1) * rstd1 * gm.x + bt.x;
            o1.y = (accO[mi][ni][3] - mu1) * rstd1 * gm.y + bt.y;
            *(float2*)(out + orow0 + c) = o0;
            *(float2*)(out + orow1 + c) = o1;
        }
    }
}

// ---------------- launch ----------------
extern "C" void kernel_launch(void* const* d_in, const int* in_sizes, int n_in,
                              void* d_out, int out_size)
{
    const float* q     = (const float*)d_in[0];
    const float* k     = (const float*)d_in[1];
    const float* v     = (const float*)d_in[2];
    const int*   mask  = (const int*)  d_in[3];
    const float* Wq    = (const float*)d_in[4];
    const float* bq    = (const float*)d_in[5];
    const float* Wk    = (const float*)d_in[6];
    const float* bk    = (const float*)d_in[7];
    const float* Wv    = (const float*)d_in[8];
    const float* bv    = (const float*)d_in[9];
    const float* gamma = (const float*)d_in[10];
    const float* beta  = (const float*)d_in[11];
    float* out = (float*)d_out;

    cudaFuncSetAttribute(attn_kernel, cudaFuncAttributeMaxDynamicSharedMemorySize, ATTN_SMEM_BYTES);

    dim3 gp(BATCH * SEQ / 128, HID / 128, 3);
    proj_kernel<<<gp, 256>>>(q, k, v, Wq, bq, Wk, bk, Wv, bv);

    dim3 ga(SEQ / QT, BATCH);
    attn_kernel<<<ga, 512, ATTN_SMEM_BYTES>>>(mask, gamma, beta, out);
}

// round 3
// speedup vs baseline: 1.3898x; 1.3898x over previous
#include <cuda_runtime.h>
#include <cstdint>
#include <cstddef>

#define BATCH 8
#define SEQ   2048
#define HID   256
#define INDIM 96
#define NKT   (SEQ / 128)

// ---------------- scratch ----------------
__device__ float g_q[BATCH * SEQ * HID];
__device__ float g_k[BATCH * SEQ * HID];
__device__ float g_v[BATCH * SEQ * HID];
__device__ float g_p[(size_t)BATCH * SEQ * SEQ];
__device__ float g_rpart[NKT * BATCH * SEQ];

// ---------------- helpers ----------------
__device__ __forceinline__ unsigned f2tf32(float x) {
    unsigned r;
    asm("cvt.rna.tf32.f32 %0, %1;" : "=r"(r) : "f"(x));
    return r;
}
__device__ __forceinline__ void split_tf32(float x, float& hi, float& lo) {
    hi = __uint_as_float(f2tf32(x));
    lo = __uint_as_float(f2tf32(x - hi));
}
__device__ __forceinline__ void mma_tf32(float c[4], const unsigned a[4], const unsigned b[2]) {
    asm("mma.sync.aligned.m16n8k8.row.col.f32.tf32.tf32.f32 "
        "{%0,%1,%2,%3}, {%4,%5,%6,%7}, {%8,%9}, {%0,%1,%2,%3};\n"
        : "+f"(c[0]), "+f"(c[1]), "+f"(c[2]), "+f"(c[3])
        : "r"(a[0]), "r"(a[1]), "r"(a[2]), "r"(a[3]), "r"(b[0]), "r"(b[1]));
}
__device__ __forceinline__ void cpa16(float* dst_smem, const float* src) {
    unsigned d = (unsigned)__cvta_generic_to_shared(dst_smem);
    asm volatile("cp.async.cg.shared.global [%0], [%1], 16;" :: "r"(d), "l"(src));
}
#define CP_COMMIT() asm volatile("cp.async.commit_group;")
#define CP_WAIT(n)  asm volatile("cp.async.wait_group %0;" :: "n"(n))

// ================= kernel 1: projections via 3xTF32 MMA =================
__global__ void __launch_bounds__(256) proj_kernel(
    const float* __restrict__ xq, const float* __restrict__ xk, const float* __restrict__ xv,
    const float* __restrict__ Wq, const float* __restrict__ bq,
    const float* __restrict__ Wk, const float* __restrict__ bk,
    const float* __restrict__ Wv, const float* __restrict__ bv)
{
    const int proj = blockIdx.z;
    const float* x; const float* W; const float* bias; float* o;
    if (proj == 0)      { x = xq; W = Wq; bias = bq; o = g_q; }
    else if (proj == 1) { x = xk; W = Wk; bias = bk; o = g_k; }
    else                { x = xv; W = Wv; bias = bv; o = g_v; }

    const int row0 = blockIdx.x * 128;
    const int h0   = blockIdx.y * 128;

    __shared__ float xs_hi[128 * 20], xs_lo[128 * 20];
    __shared__ float ws_hi[128 * 17], ws_lo[128 * 17];

    const int tid = threadIdx.x;
    const int warp = tid >> 5, lane = tid & 31;
    const int wm = warp & 3, wn = warp >> 2;
    const int tg = lane & 3, gi = lane >> 2;

    float acc[2][8][4];
#pragma unroll
    for (int mi = 0; mi < 2; mi++)
#pragma unroll
        for (int ni = 0; ni < 8; ni++)
#pragma unroll
            for (int c = 0; c < 4; c++) acc[mi][ni][c] = 0.f;

    for (int kc = 0; kc < INDIM; kc += 16) {
#pragma unroll
        for (int i = 0; i < 2; i++) {
            int f4 = tid + i * 256;
            int r = f4 >> 2, c4 = (f4 & 3) * 4;
            float4 xv4 = *(const float4*)(x + (size_t)(row0 + r) * INDIM + kc + c4);
            float h0f, l0, h1, l1, h2, l2, h3, l3;
            split_tf32(xv4.x, h0f, l0); split_tf32(xv4.y, h1, l1);
            split_tf32(xv4.z, h2, l2); split_tf32(xv4.w, h3, l3);
            float* dh = xs_hi + r * 20 + c4;
            float* dl = xs_lo + r * 20 + c4;
            dh[0] = h0f; dh[1] = h1; dh[2] = h2; dh[3] = h3;
            dl[0] = l0;  dl[1] = l1; dl[2] = l2; dl[3] = l3;
        }
#pragma unroll
        for (int i = 0; i < 2; i++) {
            int f4 = tid + i * 256;
            int k = f4 >> 5, n4 = (f4 & 31) * 4;
            float4 wv4 = *(const float4*)(W + (size_t)(kc + k) * HID + h0 + n4);
            float h0f, l0, h1, l1, h2, l2, h3, l3;
            split_tf32(wv4.x, h0f, l0); split_tf32(wv4.y, h1, l1);
            split_tf32(wv4.z, h2, l2); split_tf32(wv4.w, h3, l3);
            ws_hi[(n4 + 0) * 17 + k] = h0f; ws_lo[(n4 + 0) * 17 + k] = l0;
            ws_hi[(n4 + 1) * 17 + k] = h1;  ws_lo[(n4 + 1) * 17 + k] = l1;
            ws_hi[(n4 + 2) * 17 + k] = h2;  ws_lo[(n4 + 2) * 17 + k] = l2;
            ws_hi[(n4 + 3) * 17 + k] = h3;  ws_lo[(n4 + 3) * 17 + k] = l3;
        }
        __syncthreads();
#pragma unroll
        for (int ks = 0; ks < 16; ks += 8) {
            unsigned ah[2][4], al[2][4], bh[8][2], bl[8][2];
#pragma unroll
            for (int mi = 0; mi < 2; mi++) {
                int r = wm * 32 + mi * 16 + gi;
                ah[mi][0] = __float_as_uint(xs_hi[r * 20 + ks + tg]);
                ah[mi][1] = __float_as_uint(xs_hi[(r + 8) * 20 + ks + tg]);
                ah[mi][2] = __float_as_uint(xs_hi[r * 20 + ks + tg + 4]);
                ah[mi][3] = __float_as_uint(xs_hi[(r + 8) * 20 + ks + tg + 4]);
                al[mi][0] = __float_as_uint(xs_lo[r * 20 + ks + tg]);
                al[mi][1] = __float_as_uint(xs_lo[(r + 8) * 20 + ks + tg]);
                al[mi][2] = __float_as_uint(xs_lo[r * 20 + ks + tg + 4]);
                al[mi][3] = __float_as_uint(xs_lo[(r + 8) * 20 + ks + tg + 4]);
            }
#pragma unroll
            for (int ni = 0; ni < 8; ni++) {
                int n = wn * 64 + ni * 8 + gi;
                bh[ni][0] = __float_as_uint(ws_hi[n * 17 + ks + tg]);
                bh[ni][1] = __float_as_uint(ws_hi[n * 17 + ks + tg + 4]);
                bl[ni][0] = __float_as_uint(ws_lo[n * 17 + ks + tg]);
                bl[ni][1] = __float_as_uint(ws_lo[n * 17 + ks + tg + 4]);
            }
#pragma unroll
            for (int mi = 0; mi < 2; mi++)
#pragma unroll
                for (int ni = 0; ni < 8; ni++) {
                    mma_tf32(acc[mi][ni], ah[mi], bh[ni]);
                    mma_tf32(acc[mi][ni], ah[mi], bl[ni]);
                    mma_tf32(acc[mi][ni], al[mi], bh[ni]);
                }
        }
        __syncthreads();
    }
#pragma unroll
    for (int mi = 0; mi < 2; mi++) {
        int r0 = row0 + wm * 32 + mi * 16 + gi;
        int r1 = r0 + 8;
#pragma unroll
        for (int ni = 0; ni < 8; ni++) {
            int c = h0 + wn * 64 + ni * 8 + tg * 2;
            float2 bb = *(const float2*)(bias + c);
            *(float2*)(o + (size_t)r0 * HID + c) = make_float2(acc[mi][ni][0] + bb.x, acc[mi][ni][1] + bb.y);
            *(float2*)(o + (size_t)r1 * HID + c) = make_float2(acc[mi][ni][2] + bb.x, acc[mi][ni][3] + bb.y);
        }
    }
}

// ================= kernel 2: scores (cp.async double-buffered) =================
// grid (16 kt, 16 qt, 8 b), 256 threads (8 warps 4m x 2n). Tile 128x128, K=256.
// smem: Qbuf[2][128*36], Kbuf[2][128*36] raw fp32 (MMA truncates to tf32).
#define S_BUF (128 * 36)
#define SCORE_SMEM_BYTES ((4 * S_BUF + 256) * 4)

__global__ void __launch_bounds__(256) score_kernel(const int* __restrict__ mask)
{
    const int kt = blockIdx.x, qt = blockIdx.y, b = blockIdx.z;
    const float* Qg = g_q + ((size_t)b * SEQ + qt * 128) * HID;
    const float* Kg = g_k + ((size_t)b * SEQ + kt * 128) * HID;

    extern __shared__ float sm[];
    float* Qb[2] = { sm, sm + S_BUF };
    float* Kb[2] = { sm + 2 * S_BUF, sm + 3 * S_BUF };
    float* rsum_sm = sm + 4 * S_BUF;    // [2][128]

    const int tid = threadIdx.x;
    const int warp = tid >> 5, lane = tid & 31;
    const int wm = warp & 3, wn = warp >> 2;
    const int tg = lane & 3, gi = lane >> 2;

    // fill indices: 128 rows x 8 x 16B per tensor, 4 chunks/thread
    const int fr = tid >> 1;                  // rows handled: fr, fr+128? no: idx scheme below
    float acc[2][8][4];
#pragma unroll
    for (int mi = 0; mi < 2; mi++)
#pragma unroll
        for (int ni = 0; ni < 8; ni++)
#pragma unroll
            for (int c = 0; c < 4; c++) acc[mi][ni][c] = 0.f;
    (void)fr;

    // prefetch chunk 0
#pragma unroll
    for (int i = 0; i < 4; i++) {
        int idx = tid + i * 256;              // 0..1023
        int r = idx >> 3, c4 = (idx & 7) * 4;
        cpa16(Qb[0] + r * 36 + c4, Qg + (size_t)r * HID + c4);
        cpa16(Kb[0] + r * 36 + c4, Kg + (size_t)r * HID + c4);
    }
    CP_COMMIT();

    const int NC = HID / 32;   // 8
    for (int c = 0; c < NC; c++) {
        int cur = c & 1;
        if (c + 1 < NC) {
            int nxt = cur ^ 1, kc = (c + 1) * 32;
#pragma unroll
            for (int i = 0; i < 4; i++) {
                int idx = tid + i * 256;
                int r = idx >> 3, c4 = (idx & 7) * 4;
                cpa16(Qb[nxt] + r * 36 + c4, Qg + (size_t)r * HID + kc + c4);
                cpa16(Kb[nxt] + r * 36 + c4, Kg + (size_t)r * HID + kc + c4);
            }
            CP_COMMIT();
            CP_WAIT(1);
        } else {
            CP_WAIT(0);
        }
        __syncthreads();
        const float* Qs = Qb[cur];
        const float* Ks = Kb[cur];
#pragma unroll
        for (int ks = 0; ks < 32; ks += 8) {
            unsigned af[2][4], bf[8][2];
#pragma unroll
            for (int mi = 0; mi < 2; mi++) {
                int r = wm * 32 + mi * 16 + gi;
                af[mi][0] = __float_as_uint(Qs[r * 36 + ks + tg]);
                af[mi][1] = __float_as_uint(Qs[(r + 8) * 36 + ks + tg]);
                af[mi][2] = __float_as_uint(Qs[r * 36 + ks + tg + 4]);
                af[mi][3] = __float_as_uint(Qs[(r + 8) * 36 + ks + tg + 4]);
            }
#pragma unroll
            for (int ni = 0; ni < 8; ni++) {
                int n = wn * 64 + ni * 8 + gi;
                bf[ni][0] = __float_as_uint(Ks[n * 36 + ks + tg]);
                bf[ni][1] = __float_as_uint(Ks[n * 36 + ks + tg + 4]);
            }
#pragma unroll
            for (int mi = 0; mi < 2; mi++)
#pragma unroll
                for (int ni = 0; ni < 8; ni++)
                    mma_tf32(acc[mi][ni], af[mi], bf[ni]);
        }
        __syncthreads();
    }

    // epilogue
    const float scale = 0.0625f;
#pragma unroll
    for (int mi = 0; mi < 2; mi++) {
        int r0 = qt * 128 + wm * 32 + mi * 16 + gi;
        int r1 = r0 + 8;
        size_t base0 = ((size_t)b * SEQ + r0) * SEQ;
        size_t base1 = ((size_t)b * SEQ + r1) * SEQ;
        float rs0 = 0.f, rs1 = 0.f;
#pragma unroll
        for (int ni = 0; ni < 8; ni++) {
            int c0 = kt * 128 + wn * 64 + ni * 8 + tg * 2;
            int2 m0 = *(const int2*)(mask + base0 + c0);
            int2 m1 = *(const int2*)(mask + base1 + c0);
            float p00 = m0.x ? __expf(acc[mi][ni][0] * scale) : 0.f;
            float p01 = m0.y ? __expf(acc[mi][ni][1] * scale) : 0.f;
            float p10 = m1.x ? __expf(acc[mi][ni][2] * scale) : 0.f;
            float p11 = m1.y ? __expf(acc[mi][ni][3] * scale) : 0.f;
            *(float2*)(g_p + base0 + c0) = make_float2(p00, p01);
            *(float2*)(g_p + base1 + c0) = make_float2(p10, p11);
            rs0 += p00 + p01;
            rs1 += p10 + p11;
        }
        rs0 += __shfl_xor_sync(0xffffffffu, rs0, 1);
        rs0 += __shfl_xor_sync(0xffffffffu, rs0, 2);
        rs1 += __shfl_xor_sync(0xffffffffu, rs1, 1);
        rs1 += __shfl_xor_sync(0xffffffffu, rs1, 2);
        if (tg == 0) {
            int rl = wm * 32 + mi * 16 + gi;
            rsum_sm[wn * 128 + rl]     = rs0;
            rsum_sm[wn * 128 + rl + 8] = rs1;
        }
    }
    __syncthreads();
    if (tid < 128) {
        g_rpart[(size_t)kt * (BATCH * SEQ) + (size_t)b * SEQ + qt * 128 + tid] =
            rsum_sm[tid] + rsum_sm[128 + tid];
    }
}

// ================= kernel 3: O = (P/rowsum) V + LayerNorm (cp.async) =================
// grid (32 qs, 8 b), 256 threads (8 warps 2m x 4n). Tile 64x256, K=2048 chunks of 32.
// Pbuf stride 36 (conflict-free), Vbuf stride 260 (2-way max).
#define P_BUF (64 * 36)
#define V_BUF (32 * 260)
#define PV_SMEM_BYTES ((2 * P_BUF + 2 * V_BUF + 1024) * 4)

__global__ void __launch_bounds__(256) pv_kernel(const float* __restrict__ gamma,
                                                 const float* __restrict__ beta,
                                                 float* __restrict__ out)
{
    const int qs = blockIdx.x;
    const int b  = blockIdx.y;
    const float* Pg = g_p + ((size_t)b * SEQ + qs * 64) * SEQ;
    const float* Vg = g_v + (size_t)b * SEQ * HID;

    extern __shared__ float sm[];
    float* Pb[2] = { sm, sm + P_BUF };
    float* Vb[2] = { sm + 2 * P_BUF, sm + 2 * P_BUF + V_BUF };
    float* rstat = sm + 2 * P_BUF + 2 * V_BUF;   // 4 x 128 x 2

    const int tid = threadIdx.x;
    const int warp = tid >> 5, lane = tid & 31;
    const int wm = warp & 1, wn = warp >> 1;
    const int tg = lane & 3, gi = lane >> 2;

    float acc[2][8][4];
#pragma unroll
    for (int mi = 0; mi < 2; mi++)
#pragma unroll
        for (int ni = 0; ni < 8; ni++)
#pragma unroll
            for (int c = 0; c < 4; c++) acc[mi][ni][c] = 0.f;

    // prefetch chunk 0
#pragma unroll
    for (int i = 0; i < 2; i++) {
        int idx = tid + i * 256;              // 0..511: P 64 rows x 8 chunks
        int r = idx >> 3, c4 = (idx & 7) * 4;
        cpa16(Pb[0] + r * 36 + c4, Pg + (size_t)r * SEQ + c4);
    }
#pragma unroll
    for (int i = 0; i < 8; i++) {
        int idx = tid + i * 256;              // 0..2047: V 32 rows x 64 chunks
        int r = idx >> 6, c4 = (idx & 63) * 4;
        cpa16(Vb[0] + r * 260 + c4, Vg + (size_t)r * HID + c4);
    }
    CP_COMMIT();

    const int NC = SEQ / 32;   // 64
    for (int c = 0; c < NC; c++) {
        int cur = c & 1;
        if (c + 1 < NC) {
            int nxt = cur ^ 1, kc = (c + 1) * 32;
#pragma unroll
            for (int i = 0; i < 2; i++) {
                int idx = tid + i * 256;
                int r = idx >> 3, c4 = (idx & 7) * 4;
                cpa16(Pb[nxt] + r * 36 + c4, Pg + (size_t)r * SEQ + kc + c4);
            }
#pragma unroll
            for (int i = 0; i < 8; i++) {
                int idx = tid + i * 256;
                int r = idx >> 6, c4 = (idx & 63) * 4;
                cpa16(Vb[nxt] + r * 260 + c4, Vg + (size_t)(kc + r) * HID + c4);
            }
            CP_COMMIT();
            CP_WAIT(1);
        } else {
            CP_WAIT(0);
        }
        __syncthreads();
        const float* Ps = Pb[cur];
        const float* Vs = Vb[cur];
#pragma unroll
        for (int ks = 0; ks < 32; ks += 8) {
            unsigned af[2][4], bf[8][2];
#pragma unroll
            for (int mi = 0; mi < 2; mi++) {
                int r = wm * 32 + mi * 16 + gi;
                af[mi][0] = __float_as_uint(Ps[r * 36 + ks + tg]);
                af[mi][1] = __float_as_uint(Ps[(r + 8) * 36 + ks + tg]);
                af[mi][2] = __float_as_uint(Ps[r * 36 + ks + tg + 4]);
                af[mi][3] = __float_as_uint(Ps[(r + 8) * 36 + ks + tg + 4]);
            }
#pragma unroll
            for (int ni = 0; ni < 8; ni++) {
                int n = wn * 64 + ni * 8 + gi;
                bf[ni][0] = __float_as_uint(Vs[(ks + tg) * 260 + n]);
                bf[ni][1] = __float_as_uint(Vs[(ks + tg + 4) * 260 + n]);
            }
#pragma unroll
            for (int mi = 0; mi < 2; mi++)
#pragma unroll
                for (int ni = 0; ni < 8; ni++)
                    mma_tf32(acc[mi][ni], af[mi], bf[ni]);
        }
        __syncthreads();
    }

    // ---- normalize by rowsum ----
#pragma unroll
    for (int mi = 0; mi < 2; mi++) {
        int rl0 = wm * 32 + mi * 16 + gi;
        int rl1 = rl0 + 8;
        size_t rg0 = (size_t)b * SEQ + qs * 64 + rl0;
        size_t rg1 = (size_t)b * SEQ + qs * 64 + rl1;
        float rs0 = 0.f, rs1 = 0.f;
#pragma unroll
        for (int t = 0; t < NKT; t++) {
            rs0 += g_rpart[(size_t)t * (BATCH * SEQ) + rg0];
            rs1 += g_rpart[(size_t)t * (BATCH * SEQ) + rg1];
        }
        float i0 = 1.f / rs0, i1 = 1.f / rs1;
        float s0 = 0.f, s1 = 0.f, q0 = 0.f, q1 = 0.f;
#pragma unroll
        for (int ni = 0; ni < 8; ni++) {
            float v00 = acc[mi][ni][0] * i0; acc[mi][ni][0] = v00;
            float v01 = acc[mi][ni][1] * i0; acc[mi][ni][1] = v01;
            float v10 = acc[mi][ni][2] * i1; acc[mi][ni][2] = v10;
            float v11 = acc[mi][ni][3] * i1; acc[mi][ni][3] = v11;
            s0 += v00 + v01; s1 += v10 + v11;
            q0 += v00 * v00 + v01 * v01;
            q1 += v10 * v10 + v11 * v11;
        }
        s0 += __shfl_xor_sync(0xffffffffu, s0, 1); s0 += __shfl_xor_sync(0xffffffffu, s0, 2);
        s1 += __shfl_xor_sync(0xffffffffu, s1, 1); s1 += __shfl_xor_sync(0xffffffffu, s1, 2);
        q0 += __shfl_xor_sync(0xffffffffu, q0, 1); q0 += __shfl_xor_sync(0xffffffffu, q0, 2);
        q1 += __shfl_xor_sync(0xffffffffu, q1, 1); q1 += __shfl_xor_sync(0xffffffffu, q1, 2);
        if (tg == 0) {
            rstat[wn * 256 + rl0 * 2]     = s0;
            rstat[wn * 256 + rl0 * 2 + 1] = q0;
            rstat[wn * 256 + rl1 * 2]     = s1;
            rstat[wn * 256 + rl1 * 2 + 1] = q1;
        }
    }
    __syncthreads();

    // ---- LayerNorm + write out ----
#pragma unroll
    for (int mi = 0; mi < 2; mi++) {
        int rl0 = wm * 32 + mi * 16 + gi;
        int rl1 = rl0 + 8;
        float sum0 = rstat[rl0*2] + rstat[256 + rl0*2] + rstat[512 + rl0*2] + rstat[768 + rl0*2];
        float sq0  = rstat[rl0*2+1] + rstat[256 + rl0*2+1] + rstat[512 + rl0*2+1] + rstat[768 + rl0*2+1];
        float sum1 = rstat[rl1*2] + rstat[256 + rl1*2] + rstat[512 + rl1*2] + rstat[768 + rl1*2];
        float sq1  = rstat[rl1*2+1] + rstat[256 + rl1*2+1] + rstat[512 + rl1*2+1] + rstat[768 + rl1*2+1];
        float mu0 = sum0 * (1.f / HID);
        float mu1 = sum1 * (1.f / HID);
        float var0 = sq0 * (1.f / HID) - mu0 * mu0;
        float var1 = sq1 * (1.f / HID) - mu1 * mu1;
        float rstd0 = rsqrtf(var0 + 1e-6f);
        float rstd1 = rsqrtf(var1 + 1e-6f);
        size_t orow0 = ((size_t)b * SEQ + qs * 64 + rl0) * HID;
        size_t orow1 = ((size_t)b * SEQ + qs * 64 + rl1) * HID;
#pragma unroll
        for (int ni = 0; ni < 8; ni++) {
            int c0 = wn * 64 + ni * 8 + tg * 2;
            float2 gm = *(const float2*)(gamma + c0);
            float2 bt = *(const float2*)(beta + c0);
            float2 o0, o1;
            o0.x = (acc[mi][ni][0] - mu0) * rstd0 * gm.x + bt.x;
            o0.y = (acc[mi][ni][1] - mu0) * rstd0 * gm.y + bt.y;
            o1.x = (acc[mi][ni][2] - mu1) * rstd1 * gm.x + bt.x;
            o1.y = (acc[mi][ni][3] - mu1) * rstd1 * gm.y + bt.y;
            *(float2*)(out + orow0 + c0) = o0;
            *(float2*)(out + orow1 + c0) = o1;
        }
    }
}

// ---------------- launch ----------------
extern "C" void kernel_launch(void* const* d_in, const int* in_sizes, int n_in,
                              void* d_out, int out_size)
{
    const float* q     = (const float*)d_in[0];
    const float* k     = (const float*)d_in[1];
    const float* v     = (const float*)d_in[2];
    const int*   mask  = (const int*)  d_in[3];
    const float* Wq    = (const float*)d_in[4];
    const float* bq    = (const float*)d_in[5];
    const float* Wk    = (const float*)d_in[6];
    const float* bk    = (const float*)d_in[7];
    const float* Wv    = (const float*)d_in[8];
    const float* bv    = (const float*)d_in[9];
    const float* gamma = (const float*)d_in[10];
    const float* beta  = (const float*)d_in[11];
    float* out = (float*)d_out;

    static int inited = 0;
    if (!inited) {
        cudaFuncSetAttribute(score_kernel, cudaFuncAttributeMaxDynamicSharedMemorySize, SCORE_SMEM_BYTES);
        cudaFuncSetAttribute(pv_kernel, cudaFuncAttributeMaxDynamicSharedMemorySize, PV_SMEM_BYTES);
        inited = 1;
    }

    dim3 gp(BATCH * SEQ / 128, HID / 128, 3);
    proj_kernel<<<gp, 256>>>(q, k, v, Wq, bq, Wk, bk, Wv, bv);

    dim3 gs(SEQ / 128, SEQ / 128, BATCH);
    score_kernel<<<gs, 256, SCORE_SMEM_BYTES>>>(mask);

    dim3 go(SEQ / 64, BATCH);
    pv_kernel<<<go, 256, PV_SMEM_BYTES>>>(gamma, beta, out);
}

// round 5
// speedup vs baseline: 1.7578x; 1.2648x over previous
#include <cuda_runtime.h>
#include <cuda_fp16.h>
#include <cstdint>
#include <cstddef>

#define BATCH 8
#define SEQ   2048
#define HID   256
#define INDIM 96
#define NKT   (SEQ / 128)

// ---------------- scratch ----------------
__device__ __align__(256) float g_q[BATCH * SEQ * HID];           // tf32-valued
__device__ __align__(256) float g_k[BATCH * SEQ * HID];           // tf32-valued
__device__ __align__(256) __half g_v[BATCH * SEQ * HID];
__device__ __align__(256) __half g_p[(size_t)BATCH * SEQ * SEQ];
__device__ __align__(256) float g_rpart[NKT * BATCH * SEQ];

// ---------------- helpers ----------------
__device__ __forceinline__ unsigned f2tf32(float x) {
    unsigned r;
    asm("cvt.rna.tf32.f32 %0, %1;" : "=r"(r) : "f"(x));
    return r;
}
__device__ __forceinline__ float tf32f(float x) { return __uint_as_float(f2tf32(x)); }
__device__ __forceinline__ void split_tf32(float x, float& hi, float& lo) {
    hi = __uint_as_float(f2tf32(x));
    lo = __uint_as_float(f2tf32(x - hi));
}
__device__ __forceinline__ void mma_tf32(float c[4], const unsigned a[4], const unsigned b[2]) {
    asm("mma.sync.aligned.m16n8k8.row.col.f32.tf32.tf32.f32 "
        "{%0,%1,%2,%3}, {%4,%5,%6,%7}, {%8,%9}, {%0,%1,%2,%3};\n"
        : "+f"(c[0]), "+f"(c[1]), "+f"(c[2]), "+f"(c[3])
        : "r"(a[0]), "r"(a[1]), "r"(a[2]), "r"(a[3]), "r"(b[0]), "r"(b[1]));
}
__device__ __forceinline__ void mma_f16(float c[4], const unsigned a[4], unsigned b0, unsigned b1) {
    asm("mma.sync.aligned.m16n8k16.row.col.f32.f16.f16.f32 "
        "{%0,%1,%2,%3}, {%4,%5,%6,%7}, {%8,%9}, {%0,%1,%2,%3};\n"
        : "+f"(c[0]), "+f"(c[1]), "+f"(c[2]), "+f"(c[3])
        : "r"(a[0]), "r"(a[1]), "r"(a[2]), "r"(a[3]), "r"(b0), "r"(b1));
}
__device__ __forceinline__ void cpa16(void* dst_smem, const void* src) {
    unsigned d = (unsigned)__cvta_generic_to_shared(dst_smem);
    asm volatile("cp.async.cg.shared.global [%0], [%1], 16;" :: "r"(d), "l"(src));
}
#define CP_COMMIT() asm volatile("cp.async.commit_group;")
#define CP_WAIT(n)  asm volatile("cp.async.wait_group %0;" :: "n"(n))

__device__ __forceinline__ void ldsm_x4(unsigned r[4], const void* p) {
    unsigned a = (unsigned)__cvta_generic_to_shared(p);
    asm volatile("ldmatrix.sync.aligned.m8n8.x4.shared.b16 {%0,%1,%2,%3}, [%4];"
                 : "=r"(r[0]), "=r"(r[1]), "=r"(r[2]), "=r"(r[3]) : "r"(a));
}
__device__ __forceinline__ void ldsm_x4_t(unsigned r[4], const void* p) {
    unsigned a = (unsigned)__cvta_generic_to_shared(p);
    asm volatile("ldmatrix.sync.aligned.m8n8.x4.trans.shared.b16 {%0,%1,%2,%3}, [%4];"
                 : "=r"(r[0]), "=r"(r[1]), "=r"(r[2]), "=r"(r[3]) : "r"(a));
}

// ================= kernel 1: projections via 3xTF32 MMA =================
__global__ void __launch_bounds__(256) proj_kernel(
    const float* __restrict__ xq, const float* __restrict__ xk, const float* __restrict__ xv,
    const float* __restrict__ Wq, const float* __restrict__ bq,
    const float* __restrict__ Wk, const float* __restrict__ bk,
    const float* __restrict__ Wv, const float* __restrict__ bv)
{
    const int proj = blockIdx.z;
    const float* x; const float* W; const float* bias;
    if (proj == 0)      { x = xq; W = Wq; bias = bq; }
    else if (proj == 1) { x = xk; W = Wk; bias = bk; }
    else                { x = xv; W = Wv; bias = bv; }

    const int row0 = blockIdx.x * 128;
    const int h0   = blockIdx.y * 128;

    __shared__ float xs_hi[128 * 20], xs_lo[128 * 20];
    __shared__ float ws_hi[128 * 17], ws_lo[128 * 17];

    const int tid = threadIdx.x;
    const int warp = tid >> 5, lane = tid & 31;
    const int wm = warp & 3, wn = warp >> 2;
    const int tg = lane & 3, gi = lane >> 2;

    float acc[2][8][4];
#pragma unroll
    for (int mi = 0; mi < 2; mi++)
#pragma unroll
        for (int ni = 0; ni < 8; ni++)
#pragma unroll
            for (int c = 0; c < 4; c++) acc[mi][ni][c] = 0.f;

    for (int kc = 0; kc < INDIM; kc += 16) {
#pragma unroll
        for (int i = 0; i < 2; i++) {
            int f4 = tid + i * 256;
            int r = f4 >> 2, c4 = (f4 & 3) * 4;
            float4 xv4 = *(const float4*)(x + (size_t)(row0 + r) * INDIM + kc + c4);
            float h0f, l0, h1, l1, h2, l2, h3, l3;
            split_tf32(xv4.x, h0f, l0); split_tf32(xv4.y, h1, l1);
            split_tf32(xv4.z, h2, l2); split_tf32(xv4.w, h3, l3);
            float* dh = xs_hi + r * 20 + c4;
            float* dl = xs_lo + r * 20 + c4;
            dh[0] = h0f; dh[1] = h1; dh[2] = h2; dh[3] = h3;
            dl[0] = l0;  dl[1] = l1; dl[2] = l2; dl[3] = l3;
        }
#pragma unroll
        for (int i = 0; i < 2; i++) {
            int f4 = tid + i * 256;
            int k = f4 >> 5, n4 = (f4 & 31) * 4;
            float4 wv4 = *(const float4*)(W + (size_t)(kc + k) * HID + h0 + n4);
            float h0f, l0, h1, l1, h2, l2, h3, l3;
            split_tf32(wv4.x, h0f, l0); split_tf32(wv4.y, h1, l1);
            split_tf32(wv4.z, h2, l2); split_tf32(wv4.w, h3, l3);
            ws_hi[(n4 + 0) * 17 + k] = h0f; ws_lo[(n4 + 0) * 17 + k] = l0;
            ws_hi[(n4 + 1) * 17 + k] = h1;  ws_lo[(n4 + 1) * 17 + k] = l1;
            ws_hi[(n4 + 2) * 17 + k] = h2;  ws_lo[(n4 + 2) * 17 + k] = l2;
            ws_hi[(n4 + 3) * 17 + k] = h3;  ws_lo[(n4 + 3) * 17 + k] = l3;
        }
        __syncthreads();
#pragma unroll
        for (int ks = 0; ks < 16; ks += 8) {
            unsigned ah[2][4], al[2][4], bh[8][2], bl[8][2];
#pragma unroll
            for (int mi = 0; mi < 2; mi++) {
                int r = wm * 32 + mi * 16 + gi;
                ah[mi][0] = __float_as_uint(xs_hi[r * 20 + ks + tg]);
                ah[mi][1] = __float_as_uint(xs_hi[(r + 8) * 20 + ks + tg]);
                ah[mi][2] = __float_as_uint(xs_hi[r * 20 + ks + tg + 4]);
                ah[mi][3] = __float_as_uint(xs_hi[(r + 8) * 20 + ks + tg + 4]);
                al[mi][0] = __float_as_uint(xs_lo[r * 20 + ks + tg]);
                al[mi][1] = __float_as_uint(xs_lo[(r + 8) * 20 + ks + tg]);
                al[mi][2] = __float_as_uint(xs_lo[r * 20 + ks + tg + 4]);
                al[mi][3] = __float_as_uint(xs_lo[(r + 8) * 20 + ks + tg + 4]);
            }
#pragma unroll
            for (int ni = 0; ni < 8; ni++) {
                int n = wn * 64 + ni * 8 + gi;
                bh[ni][0] = __float_as_uint(ws_hi[n * 17 + ks + tg]);
                bh[ni][1] = __float_as_uint(ws_hi[n * 17 + ks + tg + 4]);
                bl[ni][0] = __float_as_uint(ws_lo[n * 17 + ks + tg]);
                bl[ni][1] = __float_as_uint(ws_lo[n * 17 + ks + tg + 4]);
            }
#pragma unroll
            for (int mi = 0; mi < 2; mi++)
#pragma unroll
                for (int ni = 0; ni < 8; ni++) {
                    mma_tf32(acc[mi][ni], ah[mi], bh[ni]);
                    mma_tf32(acc[mi][ni], ah[mi], bl[ni]);
                    mma_tf32(acc[mi][ni], al[mi], bh[ni]);
                }
        }
        __syncthreads();
    }
    // epilogue: +bias; q/k written tf32-rounded (score raw-feed becomes exact), v as fp16
#pragma unroll
    for (int mi = 0; mi < 2; mi++) {
        int r0 = row0 + wm * 32 + mi * 16 + gi;
        int r1 = r0 + 8;
#pragma unroll
        for (int ni = 0; ni < 8; ni++) {
            int c = h0 + wn * 64 + ni * 8 + tg * 2;
            float2 bb = *(const float2*)(bias + c);
            float v00 = acc[mi][ni][0] + bb.x, v01 = acc[mi][ni][1] + bb.y;
            float v10 = acc[mi][ni][2] + bb.x, v11 = acc[mi][ni][3] + bb.y;
            if (proj < 2) {
                float* o = proj == 0 ? g_q : g_k;
                *(float2*)(o + (size_t)r0 * HID + c) = make_float2(tf32f(v00), tf32f(v01));
                *(float2*)(o + (size_t)r1 * HID + c) = make_float2(tf32f(v10), tf32f(v11));
            } else {
                *(__half2*)(g_v + (size_t)r0 * HID + c) = __float22half2_rn(make_float2(v00, v01));
                *(__half2*)(g_v + (size_t)r1 * HID + c) = __float22half2_rn(make_float2(v10, v11));
            }
        }
    }
}

// ================= kernel 2: scores (cp.async double-buffered, P -> fp16) =================
#define S_BUF (128 * 36)
#define SCORE_SMEM_BYTES ((4 * S_BUF + 256) * 4)

__global__ void __launch_bounds__(256) score_kernel(const int* __restrict__ mask)
{
    const int kt = blockIdx.x, qt = blockIdx.y, b = blockIdx.z;
    const float* Qg = g_q + ((size_t)b * SEQ + qt * 128) * HID;
    const float* Kg = g_k + ((size_t)b * SEQ + kt * 128) * HID;

    extern __shared__ float sm[];
    float* Qb[2] = { sm, sm + S_BUF };
    float* Kb[2] = { sm + 2 * S_BUF, sm + 3 * S_BUF };
    float* rsum_sm = sm + 4 * S_BUF;

    const int tid = threadIdx.x;
    const int warp = tid >> 5, lane = tid & 31;
    const int wm = warp & 3, wn = warp >> 2;
    const int tg = lane & 3, gi = lane >> 2;

    float acc[2][8][4];
#pragma unroll
    for (int mi = 0; mi < 2; mi++)
#pragma unroll
        for (int ni = 0; ni < 8; ni++)
#pragma unroll
            for (int c = 0; c < 4; c++) acc[mi][ni][c] = 0.f;

#pragma unroll
    for (int i = 0; i < 4; i++) {
        int idx = tid + i * 256;
        int r = idx >> 3, c4 = (idx & 7) * 4;
        cpa16(Qb[0] + r * 36 + c4, Qg + (size_t)r * HID + c4);
        cpa16(Kb[0] + r * 36 + c4, Kg + (size_t)r * HID + c4);
    }
    CP_COMMIT();

    const int NC = HID / 32;
    for (int c = 0; c < NC; c++) {
        int cur = c & 1;
        if (c + 1 < NC) {
            int nxt = cur ^ 1, kc = (c + 1) * 32;
#pragma unroll
            for (int i = 0; i < 4; i++) {
                int idx = tid + i * 256;
                int r = idx >> 3, c4 = (idx & 7) * 4;
                cpa16(Qb[nxt] + r * 36 + c4, Qg + (size_t)r * HID + kc + c4);
                cpa16(Kb[nxt] + r * 36 + c4, Kg + (size_t)r * HID + kc + c4);
            }
            CP_COMMIT();
            CP_WAIT(1);
        } else {
            CP_WAIT(0);
        }
        __syncthreads();
        const float* Qs = Qb[cur];
        const float* Ks = Kb[cur];
#pragma unroll
        for (int ks = 0; ks < 32; ks += 8) {
            unsigned af[2][4], bf[8][2];
#pragma unroll
            for (int mi = 0; mi < 2; mi++) {
                int r = wm * 32 + mi * 16 + gi;
                af[mi][0] = __float_as_uint(Qs[r * 36 + ks + tg]);
                af[mi][1] = __float_as_uint(Qs[(r + 8) * 36 + ks + tg]);
                af[mi][2] = __float_as_uint(Qs[r * 36 + ks + tg + 4]);
                af[mi][3] = __float_as_uint(Qs[(r + 8) * 36 + ks + tg + 4]);
            }
#pragma unroll
            for (int ni = 0; ni < 8; ni++) {
                int n = wn * 64 + ni * 8 + gi;
                bf[ni][0] = __float_as_uint(Ks[n * 36 + ks + tg]);
                bf[ni][1] = __float_as_uint(Ks[n * 36 + ks + tg + 4]);
            }
#pragma unroll
            for (int mi = 0; mi < 2; mi++)
#pragma unroll
                for (int ni = 0; ni < 8; ni++)
                    mma_tf32(acc[mi][ni], af[mi], bf[ni]);
        }
        __syncthreads();
    }

    const float scale = 0.0625f;
#pragma unroll
    for (int mi = 0; mi < 2; mi++) {
        int r0 = qt * 128 + wm * 32 + mi * 16 + gi;
        int r1 = r0 + 8;
        size_t base0 = ((size_t)b * SEQ + r0) * SEQ;
        size_t base1 = ((size_t)b * SEQ + r1) * SEQ;
        float rs0 = 0.f, rs1 = 0.f;
#pragma unroll
        for (int ni = 0; ni < 8; ni++) {
            int c0 = kt * 128 + wn * 64 + ni * 8 + tg * 2;
            int2 m0 = *(const int2*)(mask + base0 + c0);
            int2 m1 = *(const int2*)(mask + base1 + c0);
            float p00 = m0.x ? __expf(acc[mi][ni][0] * scale) : 0.f;
            float p01 = m0.y ? __expf(acc[mi][ni][1] * scale) : 0.f;
            float p10 = m1.x ? __expf(acc[mi][ni][2] * scale) : 0.f;
            float p11 = m1.y ? __expf(acc[mi][ni][3] * scale) : 0.f;
            *(__half2*)(g_p + base0 + c0) = __float22half2_rn(make_float2(p00, p01));
            *(__half2*)(g_p + base1 + c0) = __float22half2_rn(make_float2(p10, p11));
            rs0 += p00 + p01;
            rs1 += p10 + p11;
        }
        rs0 += __shfl_xor_sync(0xffffffffu, rs0, 1);
        rs0 += __shfl_xor_sync(0xffffffffu, rs0, 2);
        rs1 += __shfl_xor_sync(0xffffffffu, rs1, 1);
        rs1 += __shfl_xor_sync(0xffffffffu, rs1, 2);
        if (tg == 0) {
            int rl = wm * 32 + mi * 16 + gi;
            rsum_sm[wn * 128 + rl]     = rs0;
            rsum_sm[wn * 128 + rl + 8] = rs1;
        }
    }
    __syncthreads();
    if (tid < 128) {
        g_rpart[(size_t)kt * (BATCH * SEQ) + (size_t)b * SEQ + qt * 128 + tid] =
            rsum_sm[tid] + rsum_sm[128 + tid];
    }
}

// ================= kernel 3: O = (P/rowsum) V fp16 MMA + LayerNorm =================
// grid (32 qs, 8 b), 256 threads (8 warps 2m x 4n). Tile 64x256, K chunks of 64.
#define PV_KT 64
#define PS_ST 72      // fp16 units; 144B = 9 granules -> conflict-free LDSM
#define VS_ST 264     // fp16 units; 528B = 33 granules -> conflict-free LDSM
#define P_BUF_H (64 * PS_ST)
#define V_BUF_H (PV_KT * VS_ST)
#define PV_SMEM_BYTES ((2 * (P_BUF_H + V_BUF_H)) * 2 + 1024 * 4)

__global__ void __launch_bounds__(256, 2) pv_kernel(const float* __restrict__ gamma,
                                                    const float* __restrict__ beta,
                                                    float* __restrict__ out)
{
    const int qs = blockIdx.x;
    const int b  = blockIdx.y;
    const __half* Pg = g_p + ((size_t)b * SEQ + qs * 64) * SEQ;
    const __half* Vg = g_v + (size_t)b * SEQ * HID;

    extern __shared__ __half smh[];
    __half* Pb[2] = { smh, smh + P_BUF_H };
    __half* Vb[2] = { smh + 2 * P_BUF_H, smh + 2 * P_BUF_H + V_BUF_H };
    float* rstat = (float*)(smh + 2 * P_BUF_H + 2 * V_BUF_H);

    const int tid = threadIdx.x;
    const int warp = tid >> 5, lane = tid & 31;
    const int wm = warp & 1, wn = warp >> 1;
    const int tg = lane & 3, gi = lane >> 2;
    const int l15 = lane & 15, lhi = (lane >> 4) << 3;

    float acc[2][8][4];
#pragma unroll
    for (int mi = 0; mi < 2; mi++)
#pragma unroll
        for (int ni = 0; ni < 8; ni++)
#pragma unroll
            for (int c = 0; c < 4; c++) acc[mi][ni][c] = 0.f;

    // prefetch chunk 0
#pragma unroll
    for (int i = 0; i < 2; i++) {
        int idx = tid + i * 256;               // 0..511: P 64 rows x 8 granules
        int r = idx >> 3, g = idx & 7;
        cpa16(Pb[0] + r * PS_ST + g * 8, Pg + (size_t)r * SEQ + g * 8);
    }
#pragma unroll
    for (int i = 0; i < 8; i++) {
        int idx = tid + i * 256;               // 0..2047: V 64 rows x 32 granules
        int r = idx >> 5, g = idx & 31;
        cpa16(Vb[0] + r * VS_ST + g * 8, Vg + (size_t)r * HID + g * 8);
    }
    CP_COMMIT();

    const int NC = SEQ / PV_KT;  // 32
    for (int c = 0; c < NC; c++) {
        int cur = c & 1;
        if (c + 1 < NC) {
            int nxt = cur ^ 1, kc = (c + 1) * PV_KT;
#pragma unroll
            for (int i = 0; i < 2; i++) {
                int idx = tid + i * 256;
                int r = idx >> 3, g = idx & 7;
                cpa16(Pb[nxt] + r * PS_ST + g * 8, Pg + (size_t)r * SEQ + kc + g * 8);
            }
#pragma unroll
            for (int i = 0; i < 8; i++) {
                int idx = tid + i * 256;
                int r = idx >> 5, g = idx & 31;
                cpa16(Vb[nxt] + r * VS_ST + g * 8, Vg + (size_t)(kc + r) * HID + g * 8);
            }
            CP_COMMIT();
            CP_WAIT(1);
        } else {
            CP_WAIT(0);
        }
        __syncthreads();
        const __half* Ps = Pb[cur];
        const __half* Vs = Vb[cur];
#pragma unroll
        for (int ks = 0; ks < PV_KT; ks += 16) {
            unsigned a[2][4], bb[4][4];
#pragma unroll
            for (int mi = 0; mi < 2; mi++)
                ldsm_x4(a[mi], Ps + (wm * 32 + mi * 16 + l15) * PS_ST + ks + lhi);
#pragma unroll
            for (int nj = 0; nj < 4; nj++)
                ldsm_x4_t(bb[nj], Vs + (size_t)(ks + l15) * VS_ST + wn * 64 + nj * 16 + lhi);
#pragma unroll
            for (int mi = 0; mi < 2; mi++)
#pragma unroll
                for (int nj = 0; nj < 4; nj++) {
                    mma_f16(acc[mi][nj * 2],     a[mi], bb[nj][0], bb[nj][1]);
                    mma_f16(acc[mi][nj * 2 + 1], a[mi], bb[nj][2], bb[nj][3]);
                }
        }
        __syncthreads();
    }

    // ---- normalize by rowsum (deterministic fixed-order sum of 16 partials) ----
#pragma unroll
    for (int mi = 0; mi < 2; mi++) {
        int rl0 = wm * 32 + mi * 16 + gi;
        int rl1 = rl0 + 8;
        size_t rg0 = (size_t)b * SEQ + qs * 64 + rl0;
        size_t rg1 = (size_t)b * SEQ + qs * 64 + rl1;
        float rs0 = 0.f, rs1 = 0.f;
#pragma unroll
        for (int t = 0; t < NKT; t++) {
            rs0 += g_rpart[(size_t)t * (BATCH * SEQ) + rg0];
            rs1 += g_rpart[(size_t)t * (BATCH * SEQ) + rg1];
        }
        float i0 = 1.f / rs0, i1 = 1.f / rs1;
        float s0 = 0.f, s1 = 0.f, q0 = 0.f, q1 = 0.f;
#pragma unroll
        for (int ni = 0; ni < 8; ni++) {
            float v00 = acc[mi][ni][0] * i0; acc[mi][ni][0] = v00;
            float v01 = acc[mi][ni][1] * i0; acc[mi][ni][1] = v01;
            float v10 = acc[mi][ni][2] * i1; acc[mi][ni][2] = v10;
            float v11 = acc[mi][ni][3] * i1; acc[mi][ni][3] = v11;
            s0 += v00 + v01; s1 += v10 + v11;
            q0 += v00 * v00 + v01 * v01;
            q1 += v10 * v10 + v11 * v11;
        }
        s0 += __shfl_xor_sync(0xffffffffu, s0, 1); s0 += __shfl_xor_sync(0xffffffffu, s0, 2);
        s1 += __shfl_xor_sync(0xffffffffu, s1, 1); s1 += __shfl_xor_sync(0xffffffffu, s1, 2);
        q0 += __shfl_xor_sync(0xffffffffu, q0, 1); q0 += __shfl_xor_sync(0xffffffffu, q0, 2);
        q1 += __shfl_xor_sync(0xffffffffu, q1, 1); q1 += __shfl_xor_sync(0xffffffffu, q1, 2);
        if (tg == 0) {
            rstat[wn * 256 + rl0 * 2]     = s0;
            rstat[wn * 256 + rl0 * 2 + 1] = q0;
            rstat[wn * 256 + rl1 * 2]     = s1;
            rstat[wn * 256 + rl1 * 2 + 1] = q1;
        }
    }
    __syncthreads();

    // ---- LayerNorm + write ----
#pragma unroll
    for (int mi = 0; mi < 2; mi++) {
        int rl0 = wm * 32 + mi * 16 + gi;
        int rl1 = rl0 + 8;
        float sum0 = rstat[rl0*2] + rstat[256 + rl0*2] + rstat[512 + rl0*2] + rstat[768 + rl0*2];
        float sq0  = rstat[rl0*2+1] + rstat[256 + rl0*2+1] + rstat[512 + rl0*2+1] + rstat[768 + rl0*2+1];
        float sum1 = rstat[rl1*2] + rstat[256 + rl1*2] + rstat[512 + rl1*2] + rstat[768 + rl1*2];
        float sq1  = rstat[rl1*2+1] + rstat[256 + rl1*2+1] + rstat[512 + rl1*2+1] + rstat[768 + rl1*2+1];
        float mu0 = sum0 * (1.f / HID);
        float mu1 = sum1 * (1.f / HID);
        float var0 = sq0 * (1.f / HID) - mu0 * mu0;
        float var1 = sq1 * (1.f / HID) - mu1 * mu1;
        float rstd0 = rsqrtf(var0 + 1e-6f);
        float rstd1 = rsqrtf(var1 + 1e-6f);
        size_t orow0 = ((size_t)b * SEQ + qs * 64 + rl0) * HID;
        size_t orow1 = ((size_t)b * SEQ + qs * 64 + rl1) * HID;
#pragma unroll
        for (int ni = 0; ni < 8; ni++) {
            int c0 = wn * 64 + ni * 8 + tg * 2;
            float2 gm = *(const float2*)(gamma + c0);
            float2 bt = *(const float2*)(beta + c0);
            float2 o0, o1;
            o0.x = (acc[mi][ni][0] - mu0) * rstd0 * gm.x + bt.x;
            o0.y = (acc[mi][ni][1] - mu0) * rstd0 * gm.y + bt.y;
            o1.x = (acc[mi][ni][2] - mu1) * rstd1 * gm.x + bt.x;
            o1.y = (acc[mi][ni][3] - mu1) * rstd1 * gm.y + bt.y;
            *(float2*)(out + orow0 + c0) = o0;
            *(float2*)(out + orow1 + c0) = o1;
        }
    }
}

// ---------------- launch ----------------
extern "C" void kernel_launch(void* const* d_in, const int* in_sizes, int n_in,
                              void* d_out, int out_size)
{
    const float* q     = (const float*)d_in[0];
    const float* k     = (const float*)d_in[1];
    const float* v     = (const float*)d_in[2];
    const int*   mask  = (const int*)  d_in[3];
    const float* Wq    = (const float*)d_in[4];
    const float* bq    = (const float*)d_in[5];
    const float* Wk    = (const float*)d_in[6];
    const float* bk    = (const float*)d_in[7];
    const float* Wv    = (const float*)d_in[8];
    const float* bv    = (const float*)d_in[9];
    const float* gamma = (const float*)d_in[10];
    const float* beta  = (const float*)d_in[11];
    float* out = (float*)d_out;

    static int inited = 0;
    if (!inited) {
        cudaFuncSetAttribute(score_kernel, cudaFuncAttributeMaxDynamicSharedMemorySize, SCORE_SMEM_BYTES);
        cudaFuncSetAttribute(pv_kernel, cudaFuncAttributeMaxDynamicSharedMemorySize, PV_SMEM_BYTES);
        inited = 1;
    }

    dim3 gp(BATCH * SEQ / 128, HID / 128, 3);
    proj_kernel<<<gp, 256>>>(q, k, v, Wq, bq, Wk, bk, Wv, bv);

    dim3 gs(SEQ / 128, SEQ / 128, BATCH);
    score_kernel<<<gs, 256, SCORE_SMEM_BYTES>>>(mask);

    dim3 go(SEQ / 64, BATCH);
    pv_kernel<<<go, 256, PV_SMEM_BYTES>>>(gamma, beta, out);
}

// round 6
// speedup vs baseline: 2.1241x; 1.2084x over previous
#include <cuda_runtime.h>
#include <cuda_fp16.h>
#include <cstdint>
#include <cstddef>

#define BATCH 8
#define SEQ   2048
#define HID   256
#define INDIM 96
#define NKT   (SEQ / 128)

// ---------------- scratch ----------------
__device__ __align__(256) __half g_q[BATCH * SEQ * HID];
__device__ __align__(256) __half g_k[BATCH * SEQ * HID];
__device__ __align__(256) __half g_v[BATCH * SEQ * HID];
__device__ __align__(256) __half g_p[(size_t)BATCH * SEQ * SEQ];
__device__ __align__(256) float g_rpart[NKT * BATCH * SEQ];

// ---------------- helpers ----------------
__device__ __forceinline__ unsigned f2tf32(float x) {
    unsigned r;
    asm("cvt.rna.tf32.f32 %0, %1;" : "=r"(r) : "f"(x));
    return r;
}
__device__ __forceinline__ void split_tf32(float x, float& hi, float& lo) {
    hi = __uint_as_float(f2tf32(x));
    lo = __uint_as_float(f2tf32(x - hi));
}
__device__ __forceinline__ void mma_tf32(float c[4], const unsigned a[4], const unsigned b[2]) {
    asm("mma.sync.aligned.m16n8k8.row.col.f32.tf32.tf32.f32 "
        "{%0,%1,%2,%3}, {%4,%5,%6,%7}, {%8,%9}, {%0,%1,%2,%3};\n"
        : "+f"(c[0]), "+f"(c[1]), "+f"(c[2]), "+f"(c[3])
        : "r"(a[0]), "r"(a[1]), "r"(a[2]), "r"(a[3]), "r"(b[0]), "r"(b[1]));
}
__device__ __forceinline__ void mma_f16(float c[4], const unsigned a[4], unsigned b0, unsigned b1) {
    asm("mma.sync.aligned.m16n8k16.row.col.f32.f16.f16.f32 "
        "{%0,%1,%2,%3}, {%4,%5,%6,%7}, {%8,%9}, {%0,%1,%2,%3};\n"
        : "+f"(c[0]), "+f"(c[1]), "+f"(c[2]), "+f"(c[3])
        : "r"(a[0]), "r"(a[1]), "r"(a[2]), "r"(a[3]), "r"(b0), "r"(b1));
}
__device__ __forceinline__ void cpa16(void* dst_smem, const void* src) {
    unsigned d = (unsigned)__cvta_generic_to_shared(dst_smem);
    asm volatile("cp.async.cg.shared.global [%0], [%1], 16;" :: "r"(d), "l"(src));
}
#define CP_COMMIT() asm volatile("cp.async.commit_group;")
#define CP_WAIT(n)  asm volatile("cp.async.wait_group %0;" :: "n"(n))

__device__ __forceinline__ void ldsm_x4(unsigned r[4], const void* p) {
    unsigned a = (unsigned)__cvta_generic_to_shared(p);
    asm volatile("ldmatrix.sync.aligned.m8n8.x4.shared.b16 {%0,%1,%2,%3}, [%4];"
                 : "=r"(r[0]), "=r"(r[1]), "=r"(r[2]), "=r"(r[3]) : "r"(a));
}
__device__ __forceinline__ void ldsm_x4_t(unsigned r[4], const void* p) {
    unsigned a = (unsigned)__cvta_generic_to_shared(p);
    asm volatile("ldmatrix.sync.aligned.m8n8.x4.trans.shared.b16 {%0,%1,%2,%3}, [%4];"
                 : "=r"(r[0]), "=r"(r[1]), "=r"(r[2]), "=r"(r[3]) : "r"(a));
}

// ================= kernel 1: projections via 3xTF32 MMA, fp16 outputs =================
__global__ void __launch_bounds__(256) proj_kernel(
    const float* __restrict__ xq, const float* __restrict__ xk, const float* __restrict__ xv,
    const float* __restrict__ Wq, const float* __restrict__ bq,
    const float* __restrict__ Wk, const float* __restrict__ bk,
    const float* __restrict__ Wv, const float* __restrict__ bv)
{
    const int proj = blockIdx.z;
    const float* x; const float* W; const float* bias; __half* o;
    if (proj == 0)      { x = xq; W = Wq; bias = bq; o = g_q; }
    else if (proj == 1) { x = xk; W = Wk; bias = bk; o = g_k; }
    else                { x = xv; W = Wv; bias = bv; o = g_v; }

    const int row0 = blockIdx.x * 128;
    const int h0   = blockIdx.y * 128;

    __shared__ float xs_hi[128 * 20], xs_lo[128 * 20];
    __shared__ float ws_hi[128 * 17], ws_lo[128 * 17];

    const int tid = threadIdx.x;
    const int warp = tid >> 5, lane = tid & 31;
    const int wm = warp & 3, wn = warp >> 2;
    const int tg = lane & 3, gi = lane >> 2;

    float acc[2][8][4];
#pragma unroll
    for (int mi = 0; mi < 2; mi++)
#pragma unroll
        for (int ni = 0; ni < 8; ni++)
#pragma unroll
            for (int c = 0; c < 4; c++) acc[mi][ni][c] = 0.f;

    for (int kc = 0; kc < INDIM; kc += 16) {
#pragma unroll
        for (int i = 0; i < 2; i++) {
            int f4 = tid + i * 256;
            int r = f4 >> 2, c4 = (f4 & 3) * 4;
            float4 xv4 = *(const float4*)(x + (size_t)(row0 + r) * INDIM + kc + c4);
            float h0f, l0, h1, l1, h2, l2, h3, l3;
            split_tf32(xv4.x, h0f, l0); split_tf32(xv4.y, h1, l1);
            split_tf32(xv4.z, h2, l2); split_tf32(xv4.w, h3, l3);
            float* dh = xs_hi + r * 20 + c4;
            float* dl = xs_lo + r * 20 + c4;
            dh[0] = h0f; dh[1] = h1; dh[2] = h2; dh[3] = h3;
            dl[0] = l0;  dl[1] = l1; dl[2] = l2; dl[3] = l3;
        }
#pragma unroll
        for (int i = 0; i < 2; i++) {
            int f4 = tid + i * 256;
            int k = f4 >> 5, n4 = (f4 & 31) * 4;
            float4 wv4 = *(const float4*)(W + (size_t)(kc + k) * HID + h0 + n4);
            float h0f, l0, h1, l1, h2, l2, h3, l3;
            split_tf32(wv4.x, h0f, l0); split_tf32(wv4.y, h1, l1);
            split_tf32(wv4.z, h2, l2); split_tf32(wv4.w, h3, l3);
            ws_hi[(n4 + 0) * 17 + k] = h0f; ws_lo[(n4 + 0) * 17 + k] = l0;
            ws_hi[(n4 + 1) * 17 + k] = h1;  ws_lo[(n4 + 1) * 17 + k] = l1;
            ws_hi[(n4 + 2) * 17 + k] = h2;  ws_lo[(n4 + 2) * 17 + k] = l2;
            ws_hi[(n4 + 3) * 17 + k] = h3;  ws_lo[(n4 + 3) * 17 + k] = l3;
        }
        __syncthreads();
#pragma unroll
        for (int ks = 0; ks < 16; ks += 8) {
            unsigned ah[2][4], al[2][4], bh[8][2], bl[8][2];
#pragma unroll
            for (int mi = 0; mi < 2; mi++) {
                int r = wm * 32 + mi * 16 + gi;
                ah[mi][0] = __float_as_uint(xs_hi[r * 20 + ks + tg]);
                ah[mi][1] = __float_as_uint(xs_hi[(r + 8) * 20 + ks + tg]);
                ah[mi][2] = __float_as_uint(xs_hi[r * 20 + ks + tg + 4]);
                ah[mi][3] = __float_as_uint(xs_hi[(r + 8) * 20 + ks + tg + 4]);
                al[mi][0] = __float_as_uint(xs_lo[r * 20 + ks + tg]);
                al[mi][1] = __float_as_uint(xs_lo[(r + 8) * 20 + ks + tg]);
                al[mi][2] = __float_as_uint(xs_lo[r * 20 + ks + tg + 4]);
                al[mi][3] = __float_as_uint(xs_lo[(r + 8) * 20 + ks + tg + 4]);
            }
#pragma unroll
            for (int ni = 0; ni < 8; ni++) {
                int n = wn * 64 + ni * 8 + gi;
                bh[ni][0] = __float_as_uint(ws_hi[n * 17 + ks + tg]);
                bh[ni][1] = __float_as_uint(ws_hi[n * 17 + ks + tg + 4]);
                bl[ni][0] = __float_as_uint(ws_lo[n * 17 + ks + tg]);
                bl[ni][1] = __float_as_uint(ws_lo[n * 17 + ks + tg + 4]);
            }
#pragma unroll
            for (int mi = 0; mi < 2; mi++)
#pragma unroll
                for (int ni = 0; ni < 8; ni++) {
                    mma_tf32(acc[mi][ni], ah[mi], bh[ni]);
                    mma_tf32(acc[mi][ni], ah[mi], bl[ni]);
                    mma_tf32(acc[mi][ni], al[mi], bh[ni]);
                }
        }
        __syncthreads();
    }
    // epilogue: +bias, fp16 store (uniform for q/k/v)
#pragma unroll
    for (int mi = 0; mi < 2; mi++) {
        int r0 = row0 + wm * 32 + mi * 16 + gi;
        int r1 = r0 + 8;
#pragma unroll
        for (int ni = 0; ni < 8; ni++) {
            int c = h0 + wn * 64 + ni * 8 + tg * 2;
            float2 bb = *(const float2*)(bias + c);
            *(__half2*)(o + (size_t)r0 * HID + c) =
                __float22half2_rn(make_float2(acc[mi][ni][0] + bb.x, acc[mi][ni][1] + bb.y));
            *(__half2*)(o + (size_t)r1 * HID + c) =
                __float22half2_rn(make_float2(acc[mi][ni][2] + bb.x, acc[mi][ni][3] + bb.y));
        }
    }
}

// ================= kernel 2: scores, fp16 MMA + ldmatrix =================
// grid (16 kt, 16 qt, 8 b), 256 threads (8 warps 4m x 2n). Tile 128x128, K=256 in chunks of 64.
#define SC_ST 72                         // halves; 144B = 9 granules (odd -> conflict-free ldsm)
#define SC_BUF (128 * SC_ST)             // halves per buffer
#define SCORE_SMEM_BYTES (4 * SC_BUF * 2 + 256 * 4)

__global__ void __launch_bounds__(256, 2) score_kernel(const int* __restrict__ mask)
{
    const int kt = blockIdx.x, qt = blockIdx.y, b = blockIdx.z;
    const __half* Qg = g_q + ((size_t)b * SEQ + qt * 128) * HID;
    const __half* Kg = g_k + ((size_t)b * SEQ + kt * 128) * HID;

    extern __shared__ __half smh[];
    __half* Qb[2] = { smh, smh + SC_BUF };
    __half* Kb[2] = { smh + 2 * SC_BUF, smh + 3 * SC_BUF };
    float* rsum_sm = (float*)(smh + 4 * SC_BUF);

    const int tid = threadIdx.x;
    const int warp = tid >> 5, lane = tid & 31;
    const int wm = warp & 3, wn = warp >> 2;
    const int tg = lane & 3, gi = lane >> 2;
    const int l15 = lane & 15, lhi = (lane >> 4) << 3;

    float acc[2][8][4];
#pragma unroll
    for (int mi = 0; mi < 2; mi++)
#pragma unroll
        for (int ni = 0; ni < 8; ni++)
#pragma unroll
            for (int c = 0; c < 4; c++) acc[mi][ni][c] = 0.f;

    // prefetch chunk 0: 128 rows x 8 granules each tensor
#pragma unroll
    for (int i = 0; i < 4; i++) {
        int idx = tid + i * 256;                 // 0..1023
        int r = idx >> 3, g = idx & 7;
        cpa16(Qb[0] + r * SC_ST + g * 8, Qg + (size_t)r * HID + g * 8);
        cpa16(Kb[0] + r * SC_ST + g * 8, Kg + (size_t)r * HID + g * 8);
    }
    CP_COMMIT();

    const int NC = HID / 64;   // 4
#pragma unroll
    for (int c = 0; c < NC; c++) {
        int cur = c & 1;
        if (c + 1 < NC) {
            int nxt = cur ^ 1, kc = (c + 1) * 64;
#pragma unroll
            for (int i = 0; i < 4; i++) {
                int idx = tid + i * 256;
                int r = idx >> 3, g = idx & 7;
                cpa16(Qb[nxt] + r * SC_ST + g * 8, Qg + (size_t)r * HID + kc + g * 8);
                cpa16(Kb[nxt] + r * SC_ST + g * 8, Kg + (size_t)r * HID + kc + g * 8);
            }
            CP_COMMIT();
            CP_WAIT(1);
        } else {
            CP_WAIT(0);
        }
        __syncthreads();
        const __half* Qs = Qb[cur];
        const __half* Ks = Kb[cur];
#pragma unroll
        for (int ks = 0; ks < 64; ks += 16) {
            unsigned a[2][4], bb[4][4];
#pragma unroll
            for (int mi = 0; mi < 2; mi++)
                ldsm_x4(a[mi], Qs + (wm * 32 + mi * 16 + l15) * SC_ST + ks + lhi);
#pragma unroll
            for (int nj = 0; nj < 4; nj++)
                ldsm_x4(bb[nj], Ks + (wn * 64 + nj * 16 + l15) * SC_ST + ks + lhi);
#pragma unroll
            for (int mi = 0; mi < 2; mi++)
#pragma unroll
                for (int nj = 0; nj < 4; nj++) {
                    mma_f16(acc[mi][nj * 2],     a[mi], bb[nj][0], bb[nj][2]);
                    mma_f16(acc[mi][nj * 2 + 1], a[mi], bb[nj][1], bb[nj][3]);
                }
        }
        __syncthreads();
    }

    // epilogue: scale, mask, exp, P (fp16), rowsum partials
    const float scale = 0.0625f;
#pragma unroll
    for (int mi = 0; mi < 2; mi++) {
        int r0 = qt * 128 + wm * 32 + mi * 16 + gi;
        int r1 = r0 + 8;
        size_t base0 = ((size_t)b * SEQ + r0) * SEQ;
        size_t base1 = ((size_t)b * SEQ + r1) * SEQ;
        float rs0 = 0.f, rs1 = 0.f;
#pragma unroll
        for (int ni = 0; ni < 8; ni++) {
            int c0 = kt * 128 + wn * 64 + ni * 8 + tg * 2;
            int2 m0 = *(const int2*)(mask + base0 + c0);
            int2 m1 = *(const int2*)(mask + base1 + c0);
            float p00 = m0.x ? __expf(acc[mi][ni][0] * scale) : 0.f;
            float p01 = m0.y ? __expf(acc[mi][ni][1] * scale) : 0.f;
            float p10 = m1.x ? __expf(acc[mi][ni][2] * scale) : 0.f;
            float p11 = m1.y ? __expf(acc[mi][ni][3] * scale) : 0.f;
            *(__half2*)(g_p + base0 + c0) = __float22half2_rn(make_float2(p00, p01));
            *(__half2*)(g_p + base1 + c0) = __float22half2_rn(make_float2(p10, p11));
            rs0 += p00 + p01;
            rs1 += p10 + p11;
        }
        rs0 += __shfl_xor_sync(0xffffffffu, rs0, 1);
        rs0 += __shfl_xor_sync(0xffffffffu, rs0, 2);
        rs1 += __shfl_xor_sync(0xffffffffu, rs1, 1);
        rs1 += __shfl_xor_sync(0xffffffffu, rs1, 2);
        if (tg == 0) {
            int rl = wm * 32 + mi * 16 + gi;
            rsum_sm[wn * 128 + rl]     = rs0;
            rsum_sm[wn * 128 + rl + 8] = rs1;
        }
    }
    __syncthreads();
    if (tid < 128) {
        g_rpart[(size_t)kt * (BATCH * SEQ) + (size_t)b * SEQ + qt * 128 + tid] =
            rsum_sm[tid] + rsum_sm[128 + tid];
    }
}

// ================= kernel 3: O = (P/rowsum) V fp16 MMA + LayerNorm =================
#define PV_KT 64
#define PS_ST 72
#define VS_ST 264
#define P_BUF_H (64 * PS_ST)
#define V_BUF_H (PV_KT * VS_ST)
#define PV_SMEM_BYTES ((2 * (P_BUF_H + V_BUF_H)) * 2 + 1024 * 4)

__global__ void __launch_bounds__(256, 2) pv_kernel(const float* __restrict__ gamma,
                                                    const float* __restrict__ beta,
                                                    float* __restrict__ out)
{
    const int qs = blockIdx.x;
    const int b  = blockIdx.y;
    const __half* Pg = g_p + ((size_t)b * SEQ + qs * 64) * SEQ;
    const __half* Vg = g_v + (size_t)b * SEQ * HID;

    extern __shared__ __half smh[];
    __half* Pb[2] = { smh, smh + P_BUF_H };
    __half* Vb[2] = { smh + 2 * P_BUF_H, smh + 2 * P_BUF_H + V_BUF_H };
    float* rstat = (float*)(smh + 2 * P_BUF_H + 2 * V_BUF_H);

    const int tid = threadIdx.x;
    const int warp = tid >> 5, lane = tid & 31;
    const int wm = warp & 1, wn = warp >> 1;
    const int tg = lane & 3, gi = lane >> 2;
    const int l15 = lane & 15, lhi = (lane >> 4) << 3;

    float acc[2][8][4];
#pragma unroll
    for (int mi = 0; mi < 2; mi++)
#pragma unroll
        for (int ni = 0; ni < 8; ni++)
#pragma unroll
            for (int c = 0; c < 4; c++) acc[mi][ni][c] = 0.f;

#pragma unroll
    for (int i = 0; i < 2; i++) {
        int idx = tid + i * 256;
        int r = idx >> 3, g = idx & 7;
        cpa16(Pb[0] + r * PS_ST + g * 8, Pg + (size_t)r * SEQ + g * 8);
    }
#pragma unroll
    for (int i = 0; i < 8; i++) {
        int idx = tid + i * 256;
        int r = idx >> 5, g = idx & 31;
        cpa16(Vb[0] + r * VS_ST + g * 8, Vg + (size_t)r * HID + g * 8);
    }
    CP_COMMIT();

    const int NC = SEQ / PV_KT;  // 32
    for (int c = 0; c < NC; c++) {
        int cur = c & 1;
        if (c + 1 < NC) {
            int nxt = cur ^ 1, kc = (c + 1) * PV_KT;
#pragma unroll
            for (int i = 0; i < 2; i++) {
                int idx = tid + i * 256;
                int r = idx >> 3, g = idx & 7;
                cpa16(Pb[nxt] + r * PS_ST + g * 8, Pg + (size_t)r * SEQ + kc + g * 8);
            }
#pragma unroll
            for (int i = 0; i < 8; i++) {
                int idx = tid + i * 256;
                int r = idx >> 5, g = idx & 31;
                cpa16(Vb[nxt] + r * VS_ST + g * 8, Vg + (size_t)(kc + r) * HID + g * 8);
            }
            CP_COMMIT();
            CP_WAIT(1);
        } else {
            CP_WAIT(0);
        }
        __syncthreads();
        const __half* Ps = Pb[cur];
        const __half* Vs = Vb[cur];
#pragma unroll
        for (int ks = 0; ks < PV_KT; ks += 16) {
            unsigned a[2][4], bb[4][4];
#pragma unroll
            for (int mi = 0; mi < 2; mi++)
                ldsm_x4(a[mi], Ps + (wm * 32 + mi * 16 + l15) * PS_ST + ks + lhi);
#pragma unroll
            for (int nj = 0; nj < 4; nj++)
                ldsm_x4_t(bb[nj], Vs + (size_t)(ks + l15) * VS_ST + wn * 64 + nj * 16 + lhi);
#pragma unroll
            for (int mi = 0; mi < 2; mi++)
#pragma unroll
                for (int nj = 0; nj < 4; nj++) {
                    mma_f16(acc[mi][nj * 2],     a[mi], bb[nj][0], bb[nj][1]);
                    mma_f16(acc[mi][nj * 2 + 1], a[mi], bb[nj][2], bb[nj][3]);
                }
        }
        __syncthreads();
    }

    // ---- normalize by rowsum ----
#pragma unroll
    for (int mi = 0; mi < 2; mi++) {
        int rl0 = wm * 32 + mi * 16 + gi;
        int rl1 = rl0 + 8;
        size_t rg0 = (size_t)b * SEQ + qs * 64 + rl0;
        size_t rg1 = (size_t)b * SEQ + qs * 64 + rl1;
        float rs0 = 0.f, rs1 = 0.f;
#pragma unroll
        for (int t = 0; t < NKT; t++) {
            rs0 += g_rpart[(size_t)t * (BATCH * SEQ) + rg0];
            rs1 += g_rpart[(size_t)t * (BATCH * SEQ) + rg1];
        }
        float i0 = 1.f / rs0, i1 = 1.f / rs1;
        float s0 = 0.f, s1 = 0.f, q0 = 0.f, q1 = 0.f;
#pragma unroll
        for (int ni = 0; ni < 8; ni++) {
            float v00 = acc[mi][ni][0] * i0; acc[mi][ni][0] = v00;
            float v01 = acc[mi][ni][1] * i0; acc[mi][ni][1] = v01;
            float v10 = acc[mi][ni][2] * i1; acc[mi][ni][2] = v10;
            float v11 = acc[mi][ni][3] * i1; acc[mi][ni][3] = v11;
            s0 += v00 + v01; s1 += v10 + v11;
            q0 += v00 * v00 + v01 * v01;
            q1 += v10 * v10 + v11 * v11;
        }
        s0 += __shfl_xor_sync(0xffffffffu, s0, 1); s0 += __shfl_xor_sync(0xffffffffu, s0, 2);
        s1 += __shfl_xor_sync(0xffffffffu, s1, 1); s1 += __shfl_xor_sync(0xffffffffu, s1, 2);
        q0 += __shfl_xor_sync(0xffffffffu, q0, 1); q0 += __shfl_xor_sync(0xffffffffu, q0, 2);
        q1 += __shfl_xor_sync(0xffffffffu, q1, 1); q1 += __shfl_xor_sync(0xffffffffu, q1, 2);
        if (tg == 0) {
            rstat[wn * 256 + rl0 * 2]     = s0;
            rstat[wn * 256 + rl0 * 2 + 1] = q0;
            rstat[wn * 256 + rl1 * 2]     = s1;
            rstat[wn * 256 + rl1 * 2 + 1] = q1;
        }
    }
    __syncthreads();

    // ---- LayerNorm + write ----
#pragma unroll
    for (int mi = 0; mi < 2; mi++) {
        int rl0 = wm * 32 + mi * 16 + gi;
        int rl1 = rl0 + 8;
        float sum0 = rstat[rl0*2] + rstat[256 + rl0*2] + rstat[512 + rl0*2] + rstat[768 + rl0*2];
        float sq0  = rstat[rl0*2+1] + rstat[256 + rl0*2+1] + rstat[512 + rl0*2+1] + rstat[768 + rl0*2+1];
        float sum1 = rstat[rl1*2] + rstat[256 + rl1*2] + rstat[512 + rl1*2] + rstat[768 + rl1*2];
        float sq1  = rstat[rl1*2+1] + rstat[256 + rl1*2+1] + rstat[512 + rl1*2+1] + rstat[768 + rl1*2+1];
        float mu0 = sum0 * (1.f / HID);
        float mu1 = sum1 * (1.f / HID);
        float var0 = sq0 * (1.f / HID) - mu0 * mu0;
        float var1 = sq1 * (1.f / HID) - mu1 * mu1;
        float rstd0 = rsqrtf(var0 + 1e-6f);
        float rstd1 = rsqrtf(var1 + 1e-6f);
        size_t orow0 = ((size_t)b * SEQ + qs * 64 + rl0) * HID;
        size_t orow1 = ((size_t)b * SEQ + qs * 64 + rl1) * HID;
#pragma unroll
        for (int ni = 0; ni < 8; ni++) {
            int c0 = wn * 64 + ni * 8 + tg * 2;
            float2 gm = *(const float2*)(gamma + c0);
            float2 bt = *(const float2*)(beta + c0);
            float2 o0, o1;
            o0.x = (acc[mi][ni][0] - mu0) * rstd0 * gm.x + bt.x;
            o0.y = (acc[mi][ni][1] - mu0) * rstd0 * gm.y + bt.y;
            o1.x = (acc[mi][ni][2] - mu1) * rstd1 * gm.x + bt.x;
            o1.y = (acc[mi][ni][3] - mu1) * rstd1 * gm.y + bt.y;
            *(float2*)(out + orow0 + c0) = o0;
            *(float2*)(out + orow1 + c0) = o1;
        }
    }
}

// ---------------- launch ----------------
extern "C" void kernel_launch(void* const* d_in, const int* in_sizes, int n_in,
                              void* d_out, int out_size)
{
    const float* q     = (const float*)d_in[0];
    const float* k     = (const float*)d_in[1];
    const float* v     = (const float*)d_in[2];
    const int*   mask  = (const int*)  d_in[3];
    const float* Wq    = (const float*)d_in[4];
    const float* bq    = (const float*)d_in[5];
    const float* Wk    = (const float*)d_in[6];
    const float* bk    = (const float*)d_in[7];
    const float* Wv    = (const float*)d_in[8];
    const float* bv    = (const float*)d_in[9];
    const float* gamma = (const float*)d_in[10];
    const float* beta  = (const float*)d_in[11];
    float* out = (float*)d_out;

    static int inited = 0;
    if (!inited) {
        cudaFuncSetAttribute(score_kernel, cudaFuncAttributeMaxDynamicSharedMemorySize, SCORE_SMEM_BYTES);
        cudaFuncSetAttribute(pv_kernel, cudaFuncAttributeMaxDynamicSharedMemorySize, PV_SMEM_BYTES);
        inited = 1;
    }

    dim3 gp(BATCH * SEQ / 128, HID / 128, 3);
    proj_kernel<<<gp, 256>>>(q, k, v, Wq, bq, Wk, bk, Wv, bv);

    dim3 gs(SEQ / 128, SEQ / 128, BATCH);
    score_kernel<<<gs, 256, SCORE_SMEM_BYTES>>>(mask);

    dim3 go(SEQ / 64, BATCH);
    pv_kernel<<<go, 256, PV_SMEM_BYTES>>>(gamma, beta, out);
}

// round 7
// speedup vs baseline: 2.1853x; 1.0288x over previous
#include <cuda_runtime.h>
#include <cuda_fp16.h>
#include <cstdint>
#include <cstddef>

#define BATCH 8
#define SEQ   2048
#define HID   256
#define INDIM 96
#define NKT   (SEQ / 128)

// ---------------- scratch ----------------
__device__ __align__(256) __half g_q[BATCH * SEQ * HID];
__device__ __align__(256) __half g_k[BATCH * SEQ * HID];
__device__ __align__(256) __half g_v[BATCH * SEQ * HID];
__device__ __align__(256) __half g_p[(size_t)BATCH * SEQ * SEQ];
__device__ __align__(256) float g_rpart[NKT * BATCH * SEQ];

// ---------------- helpers ----------------
__device__ __forceinline__ unsigned f2tf32(float x) {
    unsigned r;
    asm("cvt.rna.tf32.f32 %0, %1;" : "=r"(r) : "f"(x));
    return r;
}
__device__ __forceinline__ void split_tf32(float x, float& hi, float& lo) {
    hi = __uint_as_float(f2tf32(x));
    lo = __uint_as_float(f2tf32(x - hi));
}
__device__ __forceinline__ void mma_tf32(float c[4], const unsigned a[4], const unsigned b[2]) {
    asm("mma.sync.aligned.m16n8k8.row.col.f32.tf32.tf32.f32 "
        "{%0,%1,%2,%3}, {%4,%5,%6,%7}, {%8,%9}, {%0,%1,%2,%3};\n"
        : "+f"(c[0]), "+f"(c[1]), "+f"(c[2]), "+f"(c[3])
        : "r"(a[0]), "r"(a[1]), "r"(a[2]), "r"(a[3]), "r"(b[0]), "r"(b[1]));
}
__device__ __forceinline__ void mma_f16(float c[4], const unsigned a[4], unsigned b0, unsigned b1) {
    asm("mma.sync.aligned.m16n8k16.row.col.f32.f16.f16.f32 "
        "{%0,%1,%2,%3}, {%4,%5,%6,%7}, {%8,%9}, {%0,%1,%2,%3};\n"
        : "+f"(c[0]), "+f"(c[1]), "+f"(c[2]), "+f"(c[3])
        : "r"(a[0]), "r"(a[1]), "r"(a[2]), "r"(a[3]), "r"(b0), "r"(b1));
}
__device__ __forceinline__ void cpa16(void* dst_smem, const void* src) {
    unsigned d = (unsigned)__cvta_generic_to_shared(dst_smem);
    asm volatile("cp.async.cg.shared.global [%0], [%1], 16;" :: "r"(d), "l"(src));
}
#define CP_COMMIT() asm volatile("cp.async.commit_group;")
#define CP_WAIT(n)  asm volatile("cp.async.wait_group %0;" :: "n"(n))

__device__ __forceinline__ void ldsm_x4(unsigned r[4], const void* p) {
    unsigned a = (unsigned)__cvta_generic_to_shared(p);
    asm volatile("ldmatrix.sync.aligned.m8n8.x4.shared.b16 {%0,%1,%2,%3}, [%4];"
                 : "=r"(r[0]), "=r"(r[1]), "=r"(r[2]), "=r"(r[3]) : "r"(a));
}
__device__ __forceinline__ void ldsm_x4_t(unsigned r[4], const void* p) {
    unsigned a = (unsigned)__cvta_generic_to_shared(p);
    asm volatile("ldmatrix.sync.aligned.m8n8.x4.trans.shared.b16 {%0,%1,%2,%3}, [%4];"
                 : "=r"(r[0]), "=r"(r[1]), "=r"(r[2]), "=r"(r[3]) : "r"(a));
}

// ================= kernel 1: projections via 3xTF32 MMA, fp16 outputs =================
// W kept in natural [k][n] layout, stride 132: conflict-free float4 fills AND
// conflict-free b-frag loads (bank = gi + 4*tg + const). 2 CTAs/SM forced.
#define WS_ST 132
__global__ void __launch_bounds__(256, 2) proj_kernel(
    const float* __restrict__ xq, const float* __restrict__ xk, const float* __restrict__ xv,
    const float* __restrict__ Wq, const float* __restrict__ bq,
    const float* __restrict__ Wk, const float* __restrict__ bk,
    const float* __restrict__ Wv, const float* __restrict__ bv)
{
    const int proj = blockIdx.z;
    const float* x; const float* W; const float* bias; __half* o;
    if (proj == 0)      { x = xq; W = Wq; bias = bq; o = g_q; }
    else if (proj == 1) { x = xk; W = Wk; bias = bk; o = g_k; }
    else                { x = xv; W = Wv; bias = bv; o = g_v; }

    const int row0 = blockIdx.x * 128;
    const int h0   = blockIdx.y * 128;

    __shared__ float xs_hi[128 * 20], xs_lo[128 * 20];     // [r][k]
    __shared__ float ws_hi[16 * WS_ST], ws_lo[16 * WS_ST]; // [k][n]

    const int tid = threadIdx.x;
    const int warp = tid >> 5, lane = tid & 31;
    const int wm = warp & 3, wn = warp >> 2;
    const int tg = lane & 3, gi = lane >> 2;

    float acc[2][8][4];
#pragma unroll
    for (int mi = 0; mi < 2; mi++)
#pragma unroll
        for (int ni = 0; ni < 8; ni++)
#pragma unroll
            for (int c = 0; c < 4; c++) acc[mi][ni][c] = 0.f;

    for (int kc = 0; kc < INDIM; kc += 16) {
        // x tile: 128 rows x 16 cols, hi/lo split, [r][k] stride 20
#pragma unroll
        for (int i = 0; i < 2; i++) {
            int f4 = tid + i * 256;
            int r = f4 >> 2, c4 = (f4 & 3) * 4;
            float4 xv4 = *(const float4*)(x + (size_t)(row0 + r) * INDIM + kc + c4);
            float h0f, l0, h1, l1, h2, l2, h3, l3;
            split_tf32(xv4.x, h0f, l0); split_tf32(xv4.y, h1, l1);
            split_tf32(xv4.z, h2, l2); split_tf32(xv4.w, h3, l3);
            float* dh = xs_hi + r * 20 + c4;
            float* dl = xs_lo + r * 20 + c4;
            dh[0] = h0f; dh[1] = h1; dh[2] = h2; dh[3] = h3;
            dl[0] = l0;  dl[1] = l1; dl[2] = l2; dl[3] = l3;
        }
        // W tile: 16 k-rows x 128 cols, NATURAL [k][n] layout, float4 stores
#pragma unroll
        for (int i = 0; i < 2; i++) {
            int f4 = tid + i * 256;
            int k = f4 >> 5, n4 = (f4 & 31) * 4;
            float4 wv4 = *(const float4*)(W + (size_t)(kc + k) * HID + h0 + n4);
            float h0f, l0, h1, l1, h2, l2, h3, l3;
            split_tf32(wv4.x, h0f, l0); split_tf32(wv4.y, h1, l1);
            split_tf32(wv4.z, h2, l2); split_tf32(wv4.w, h3, l3);
            *(float4*)(ws_hi + k * WS_ST + n4) = make_float4(h0f, h1, h2, h3);
            *(float4*)(ws_lo + k * WS_ST + n4) = make_float4(l0, l1, l2, l3);
        }
        __syncthreads();
#pragma unroll
        for (int ks = 0; ks < 16; ks += 8) {
            unsigned ah[2][4], al[2][4], bh[8][2], bl[8][2];
#pragma unroll
            for (int mi = 0; mi < 2; mi++) {
                int r = wm * 32 + mi * 16 + gi;
                ah[mi][0] = __float_as_uint(xs_hi[r * 20 + ks + tg]);
                ah[mi][1] = __float_as_uint(xs_hi[(r + 8) * 20 + ks + tg]);
                ah[mi][2] = __float_as_uint(xs_hi[r * 20 + ks + tg + 4]);
                ah[mi][3] = __float_as_uint(xs_hi[(r + 8) * 20 + ks + tg + 4]);
                al[mi][0] = __float_as_uint(xs_lo[r * 20 + ks + tg]);
                al[mi][1] = __float_as_uint(xs_lo[(r + 8) * 20 + ks + tg]);
                al[mi][2] = __float_as_uint(xs_lo[r * 20 + ks + tg + 4]);
                al[mi][3] = __float_as_uint(xs_lo[(r + 8) * 20 + ks + tg + 4]);
            }
#pragma unroll
            for (int ni = 0; ni < 8; ni++) {
                int n = wn * 64 + ni * 8 + gi;
                bh[ni][0] = __float_as_uint(ws_hi[(ks + tg) * WS_ST + n]);
                bh[ni][1] = __float_as_uint(ws_hi[(ks + tg + 4) * WS_ST + n]);
                bl[ni][0] = __float_as_uint(ws_lo[(ks + tg) * WS_ST + n]);
                bl[ni][1] = __float_as_uint(ws_lo[(ks + tg + 4) * WS_ST + n]);
            }
#pragma unroll
            for (int mi = 0; mi < 2; mi++)
#pragma unroll
                for (int ni = 0; ni < 8; ni++) {
                    mma_tf32(acc[mi][ni], ah[mi], bh[ni]);
                    mma_tf32(acc[mi][ni], ah[mi], bl[ni]);
                    mma_tf32(acc[mi][ni], al[mi], bh[ni]);
                }
        }
        __syncthreads();
    }
    // epilogue: +bias, fp16 store
#pragma unroll
    for (int mi = 0; mi < 2; mi++) {
        int r0 = row0 + wm * 32 + mi * 16 + gi;
        int r1 = r0 + 8;
#pragma unroll
        for (int ni = 0; ni < 8; ni++) {
            int c = h0 + wn * 64 + ni * 8 + tg * 2;
            float2 bb = *(const float2*)(bias + c);
            *(__half2*)(o + (size_t)r0 * HID + c) =
                __float22half2_rn(make_float2(acc[mi][ni][0] + bb.x, acc[mi][ni][1] + bb.y));
            *(__half2*)(o + (size_t)r1 * HID + c) =
                __float22half2_rn(make_float2(acc[mi][ni][2] + bb.x, acc[mi][ni][3] + bb.y));
        }
    }
}

// ================= kernel 2: scores, fp16 MMA + ldmatrix =================
#define SC_ST 72
#define SC_BUF (128 * SC_ST)
#define SCORE_SMEM_BYTES (4 * SC_BUF * 2 + 256 * 4)

__global__ void __launch_bounds__(256, 2) score_kernel(const int* __restrict__ mask)
{
    const int kt = blockIdx.x, qt = blockIdx.y, b = blockIdx.z;
    const __half* Qg = g_q + ((size_t)b * SEQ + qt * 128) * HID;
    const __half* Kg = g_k + ((size_t)b * SEQ + kt * 128) * HID;

    extern __shared__ __half smh[];
    __half* Qb[2] = { smh, smh + SC_BUF };
    __half* Kb[2] = { smh + 2 * SC_BUF, smh + 3 * SC_BUF };
    float* rsum_sm = (float*)(smh + 4 * SC_BUF);

    const int tid = threadIdx.x;
    const int warp = tid >> 5, lane = tid & 31;
    const int wm = warp & 3, wn = warp >> 2;
    const int tg = lane & 3, gi = lane >> 2;
    const int l15 = lane & 15, lhi = (lane >> 4) << 3;

    float acc[2][8][4];
#pragma unroll
    for (int mi = 0; mi < 2; mi++)
#pragma unroll
        for (int ni = 0; ni < 8; ni++)
#pragma unroll
            for (int c = 0; c < 4; c++) acc[mi][ni][c] = 0.f;

#pragma unroll
    for (int i = 0; i < 4; i++) {
        int idx = tid + i * 256;
        int r = idx >> 3, g = idx & 7;
        cpa16(Qb[0] + r * SC_ST + g * 8, Qg + (size_t)r * HID + g * 8);
        cpa16(Kb[0] + r * SC_ST + g * 8, Kg + (size_t)r * HID + g * 8);
    }
    CP_COMMIT();

    const int NC = HID / 64;
#pragma unroll
    for (int c = 0; c < NC; c++) {
        int cur = c & 1;
        if (c + 1 < NC) {
            int nxt = cur ^ 1, kc = (c + 1) * 64;
#pragma unroll
            for (int i = 0; i < 4; i++) {
                int idx = tid + i * 256;
                int r = idx >> 3, g = idx & 7;
                cpa16(Qb[nxt] + r * SC_ST + g * 8, Qg + (size_t)r * HID + kc + g * 8);
                cpa16(Kb[nxt] + r * SC_ST + g * 8, Kg + (size_t)r * HID + kc + g * 8);
            }
            CP_COMMIT();
            CP_WAIT(1);
        } else {
            CP_WAIT(0);
        }
        __syncthreads();
        const __half* Qs = Qb[cur];
        const __half* Ks = Kb[cur];
#pragma unroll
        for (int ks = 0; ks < 64; ks += 16) {
            unsigned a[2][4], bb[4][4];
#pragma unroll
            for (int mi = 0; mi < 2; mi++)
                ldsm_x4(a[mi], Qs + (wm * 32 + mi * 16 + l15) * SC_ST + ks + lhi);
#pragma unroll
            for (int nj = 0; nj < 4; nj++)
                ldsm_x4(bb[nj], Ks + (wn * 64 + nj * 16 + l15) * SC_ST + ks + lhi);
#pragma unroll
            for (int mi = 0; mi < 2; mi++)
#pragma unroll
                for (int nj = 0; nj < 4; nj++) {
                    mma_f16(acc[mi][nj * 2],     a[mi], bb[nj][0], bb[nj][2]);
                    mma_f16(acc[mi][nj * 2 + 1], a[mi], bb[nj][1], bb[nj][3]);
                }
        }
        __syncthreads();
    }

    const float scale = 0.0625f;
#pragma unroll
    for (int mi = 0; mi < 2; mi++) {
        int r0 = qt * 128 + wm * 32 + mi * 16 + gi;
        int r1 = r0 + 8;
        size_t base0 = ((size_t)b * SEQ + r0) * SEQ;
        size_t base1 = ((size_t)b * SEQ + r1) * SEQ;
        float rs0 = 0.f, rs1 = 0.f;
#pragma unroll
        for (int ni = 0; ni < 8; ni++) {
            int c0 = kt * 128 + wn * 64 + ni * 8 + tg * 2;
            int2 m0 = *(const int2*)(mask + base0 + c0);
            int2 m1 = *(const int2*)(mask + base1 + c0);
            float p00 = m0.x ? __expf(acc[mi][ni][0] * scale) : 0.f;
            float p01 = m0.y ? __expf(acc[mi][ni][1] * scale) : 0.f;
            float p10 = m1.x ? __expf(acc[mi][ni][2] * scale) : 0.f;
            float p11 = m1.y ? __expf(acc[mi][ni][3] * scale) : 0.f;
            *(__half2*)(g_p + base0 + c0) = __float22half2_rn(make_float2(p00, p01));
            *(__half2*)(g_p + base1 + c0) = __float22half2_rn(make_float2(p10, p11));
            rs0 += p00 + p01;
            rs1 += p10 + p11;
        }
        rs0 += __shfl_xor_sync(0xffffffffu, rs0, 1);
        rs0 += __shfl_xor_sync(0xffffffffu, rs0, 2);
        rs1 += __shfl_xor_sync(0xffffffffu, rs1, 1);
        rs1 += __shfl_xor_sync(0xffffffffu, rs1, 2);
        if (tg == 0) {
            int rl = wm * 32 + mi * 16 + gi;
            rsum_sm[wn * 128 + rl]     = rs0;
            rsum_sm[wn * 128 + rl + 8] = rs1;
        }
    }
    __syncthreads();
    if (tid < 128) {
        g_rpart[(size_t)kt * (BATCH * SEQ) + (size_t)b * SEQ + qt * 128 + tid] =
            rsum_sm[tid] + rsum_sm[128 + tid];
    }
}

// ================= kernel 3: O = (P/rowsum) V fp16 MMA + LayerNorm =================
#define PV_KT 64
#define PS_ST 72
#define VS_ST 264
#define P_BUF_H (64 * PS_ST)
#define V_BUF_H (PV_KT * VS_ST)
#define PV_SMEM_BYTES ((2 * (P_BUF_H + V_BUF_H)) * 2 + 1024 * 4)

__global__ void __launch_bounds__(256, 2) pv_kernel(const float* __restrict__ gamma,
                                                    const float* __restrict__ beta,
                                                    float* __restrict__ out)
{
    const int qs = blockIdx.x;
    const int b  = blockIdx.y;
    const __half* Pg = g_p + ((size_t)b * SEQ + qs * 64) * SEQ;
    const __half* Vg = g_v + (size_t)b * SEQ * HID;

    extern __shared__ __half smh[];
    __half* Pb[2] = { smh, smh + P_BUF_H };
    __half* Vb[2] = { smh + 2 * P_BUF_H, smh + 2 * P_BUF_H + V_BUF_H };
    float* rstat = (float*)(smh + 2 * P_BUF_H + 2 * V_BUF_H);

    const int tid = threadIdx.x;
    const int warp = tid >> 5, lane = tid & 31;
    const int wm = warp & 1, wn = warp >> 1;
    const int tg = lane & 3, gi = lane >> 2;
    const int l15 = lane & 15, lhi = (lane >> 4) << 3;

    float acc[2][8][4];
#pragma unroll
    for (int mi = 0; mi < 2; mi++)
#pragma unroll
        for (int ni = 0; ni < 8; ni++)
#pragma unroll
            for (int c = 0; c < 4; c++) acc[mi][ni][c] = 0.f;

#pragma unroll
    for (int i = 0; i < 2; i++) {
        int idx = tid + i * 256;
        int r = idx >> 3, g = idx & 7;
        cpa16(Pb[0] + r * PS_ST + g * 8, Pg + (size_t)r * SEQ + g * 8);
    }
#pragma unroll
    for (int i = 0; i < 8; i++) {
        int idx = tid + i * 256;
        int r = idx >> 5, g = idx & 31;
        cpa16(Vb[0] + r * VS_ST + g * 8, Vg + (size_t)r * HID + g * 8);
    }
    CP_COMMIT();

    const int NC = SEQ / PV_KT;  // 32
    for (int c = 0; c < NC; c++) {
        int cur = c & 1;
        if (c + 1 < NC) {
            int nxt = cur ^ 1, kc = (c + 1) * PV_KT;
#pragma unroll
            for (int i = 0; i < 2; i++) {
                int idx = tid + i * 256;
                int r = idx >> 3, g = idx & 7;
                cpa16(Pb[nxt] + r * PS_ST + g * 8, Pg + (size_t)r * SEQ + kc + g * 8);
            }
#pragma unroll
            for (int i = 0; i < 8; i++) {
                int idx = tid + i * 256;
                int r = idx >> 5, g = idx & 31;
                cpa16(Vb[nxt] + r * VS_ST + g * 8, Vg + (size_t)(kc + r) * HID + g * 8);
            }
            CP_COMMIT();
            CP_WAIT(1);
        } else {
            CP_WAIT(0);
        }
        __syncthreads();
        const __half* Ps = Pb[cur];
        const __half* Vs = Vb[cur];
#pragma unroll
        for (int ks = 0; ks < PV_KT; ks += 16) {
            unsigned a[2][4], bb[4][4];
#pragma unroll
            for (int mi = 0; mi < 2; mi++)
                ldsm_x4(a[mi], Ps + (wm * 32 + mi * 16 + l15) * PS_ST + ks + lhi);
#pragma unroll
            for (int nj = 0; nj < 4; nj++)
                ldsm_x4_t(bb[nj], Vs + (size_t)(ks + l15) * VS_ST + wn * 64 + nj * 16 + lhi);
#pragma unroll
            for (int mi = 0; mi < 2; mi++)
#pragma unroll
                for (int nj = 0; nj < 4; nj++) {
                    mma_f16(acc[mi][nj * 2],     a[mi], bb[nj][0], bb[nj][1]);
                    mma_f16(acc[mi][nj * 2 + 1], a[mi], bb[nj][2], bb[nj][3]);
                }
        }
        __syncthreads();
    }

    // ---- normalize by rowsum ----
#pragma unroll
    for (int mi = 0; mi < 2; mi++) {
        int rl0 = wm * 32 + mi * 16 + gi;
        int rl1 = rl0 + 8;
        size_t rg0 = (size_t)b * SEQ + qs * 64 + rl0;
        size_t rg1 = (size_t)b * SEQ + qs * 64 + rl1;
        float rs0 = 0.f, rs1 = 0.f;
#pragma unroll
        for (int t = 0; t < NKT; t++) {
            rs0 += g_rpart[(size_t)t * (BATCH * SEQ) + rg0];
            rs1 += g_rpart[(size_t)t * (BATCH * SEQ) + rg1];
        }
        float i0 = 1.f / rs0, i1 = 1.f / rs1;
        float s0 = 0.f, s1 = 0.f, q0 = 0.f, q1 = 0.f;
#pragma unroll
        for (int ni = 0; ni < 8; ni++) {
            float v00 = acc[mi][ni][0] * i0; acc[mi][ni][0] = v00;
            float v01 = acc[mi][ni][1] * i0; acc[mi][ni][1] = v01;
            float v10 = acc[mi][ni][2] * i1; acc[mi][ni][2] = v10;
            float v11 = acc[mi][ni][3] * i1; acc[mi][ni][3] = v11;
            s0 += v00 + v01; s1 += v10 + v11;
            q0 += v00 * v00 + v01 * v01;
            q1 += v10 * v10 + v11 * v11;
        }
        s0 += __shfl_xor_sync(0xffffffffu, s0, 1); s0 += __shfl_xor_sync(0xffffffffu, s0, 2);
        s1 += __shfl_xor_sync(0xffffffffu, s1, 1); s1 += __shfl_xor_sync(0xffffffffu, s1, 2);
        q0 += __shfl_xor_sync(0xffffffffu, q0, 1); q0 += __shfl_xor_sync(0xffffffffu, q0, 2);
        q1 += __shfl_xor_sync(0xffffffffu, q1, 1); q1 += __shfl_xor_sync(0xffffffffu, q1, 2);
        if (tg == 0) {
            rstat[wn * 256 + rl0 * 2]     = s0;
            rstat[wn * 256 + rl0 * 2 + 1] = q0;
            rstat[wn * 256 + rl1 * 2]     = s1;
            rstat[wn * 256 + rl1 * 2 + 1] = q1;
        }
    }
    __syncthreads();

    // ---- LayerNorm + write ----
#pragma unroll
    for (int mi = 0; mi < 2; mi++) {
        int rl0 = wm * 32 + mi * 16 + gi;
        int rl1 = rl0 + 8;
        float sum0 = rstat[rl0*2] + rstat[256 + rl0*2] + rstat[512 + rl0*2] + rstat[768 + rl0*2];
        float sq0  = rstat[rl0*2+1] + rstat[256 + rl0*2+1] + rstat[512 + rl0*2+1] + rstat[768 + rl0*2+1];
        float sum1 = rstat[rl1*2] + rstat[256 + rl1*2] + rstat[512 + rl1*2] + rstat[768 + rl1*2];
        float sq1  = rstat[rl1*2+1] + rstat[256 + rl1*2+1] + rstat[512 + rl1*2+1] + rstat[768 + rl1*2+1];
        float mu0 = sum0 * (1.f / HID);
        float mu1 = sum1 * (1.f / HID);
        float var0 = sq0 * (1.f / HID) - mu0 * mu0;
        float var1 = sq1 * (1.f / HID) - mu1 * mu1;
        float rstd0 = rsqrtf(var0 + 1e-6f);
        float rstd1 = rsqrtf(var1 + 1e-6f);
        size_t orow0 = ((size_t)b * SEQ + qs * 64 + rl0) * HID;
        size_t orow1 = ((size_t)b * SEQ + qs * 64 + rl1) * HID;
#pragma unroll
        for (int ni = 0; ni < 8; ni++) {
            int c0 = wn * 64 + ni * 8 + tg * 2;
            float2 gm = *(const float2*)(gamma + c0);
            float2 bt = *(const float2*)(beta + c0);
            float2 o0, o1;
            o0.x = (acc[mi][ni][0] - mu0) * rstd0 * gm.x + bt.x;
            o0.y = (acc[mi][ni][1] - mu0) * rstd0 * gm.y + bt.y;
            o1.x = (acc[mi][ni][2] - mu1) * rstd1 * gm.x + bt.x;
            o1.y = (acc[mi][ni][3] - mu1) * rstd1 * gm.y + bt.y;
            *(float2*)(out + orow0 + c0) = o0;
            *(float2*)(out + orow1 + c0) = o1;
        }
    }
}

// ---------------- launch ----------------
extern "C" void kernel_launch(void* const* d_in, const int* in_sizes, int n_in,
                              void* d_out, int out_size)
{
    const float* q     = (const float*)d_in[0];
    const float* k     = (const float*)d_in[1];
    const float* v     = (const float*)d_in[2];
    const int*   mask  = (const int*)  d_in[3];
    const float* Wq    = (const float*)d_in[4];
    const float* bq    = (const float*)d_in[5];
    const float* Wk    = (const float*)d_in[6];
    const float* bk    = (const float*)d_in[7];
    const float* Wv    = (const float*)d_in[8];
    const float* bv    = (const float*)d_in[9];
    const float* gamma = (const float*)d_in[10];
    const float* beta  = (const float*)d_in[11];
    float* out = (float*)d_out;

    static int inited = 0;
    if (!inited) {
        cudaFuncSetAttribute(score_kernel, cudaFuncAttributeMaxDynamicSharedMemorySize, SCORE_SMEM_BYTES);
        cudaFuncSetAttribute(pv_kernel, cudaFuncAttributeMaxDynamicSharedMemorySize, PV_SMEM_BYTES);
        inited = 1;
    }

    dim3 gp(BATCH * SEQ / 128, HID / 128, 3);
    proj_kernel<<<gp, 256>>>(q, k, v, Wq, bq, Wk, bk, Wv, bv);

    dim3 gs(SEQ / 128, SEQ / 128, BATCH);
    score_kernel<<<gs, 256, SCORE_SMEM_BYTES>>>(mask);

    dim3 go(SEQ / 64, BATCH);
    pv_kernel<<<go, 256, PV_SMEM_BYTES>>>(gamma, beta, out);
}

// round 8
// speedup vs baseline: 2.2818x; 1.0442x over previous
#include <cuda_runtime.h>
#include <cuda_fp16.h>
#include <cstdint>
#include <cstddef>

#define BATCH 8
#define SEQ   2048
#define HID   256
#define INDIM 96

// ---------------- scratch ----------------
__device__ __align__(256) __half g_q[BATCH * SEQ * HID];
__device__ __align__(256) __half g_k[BATCH * SEQ * HID];
__device__ __align__(256) __half g_v[BATCH * SEQ * HID];

// ---------------- helpers ----------------
__device__ __forceinline__ unsigned f2tf32(float x) {
    unsigned r;
    asm("cvt.rna.tf32.f32 %0, %1;" : "=r"(r) : "f"(x));
    return r;
}
__device__ __forceinline__ void split_tf32(float x, float& hi, float& lo) {
    hi = __uint_as_float(f2tf32(x));
    lo = __uint_as_float(f2tf32(x - hi));
}
__device__ __forceinline__ void mma_tf32(float c[4], const unsigned a[4], const unsigned b[2]) {
    asm("mma.sync.aligned.m16n8k8.row.col.f32.tf32.tf32.f32 "
        "{%0,%1,%2,%3}, {%4,%5,%6,%7}, {%8,%9}, {%0,%1,%2,%3};\n"
        : "+f"(c[0]), "+f"(c[1]), "+f"(c[2]), "+f"(c[3])
        : "r"(a[0]), "r"(a[1]), "r"(a[2]), "r"(a[3]), "r"(b[0]), "r"(b[1]));
}
__device__ __forceinline__ void mma_f16(float c[4], const unsigned a[4], unsigned b0, unsigned b1) {
    asm("mma.sync.aligned.m16n8k16.row.col.f32.f16.f16.f32 "
        "{%0,%1,%2,%3}, {%4,%5,%6,%7}, {%8,%9}, {%0,%1,%2,%3};\n"
        : "+f"(c[0]), "+f"(c[1]), "+f"(c[2]), "+f"(c[3])
        : "r"(a[0]), "r"(a[1]), "r"(a[2]), "r"(a[3]), "r"(b0), "r"(b1));
}
__device__ __forceinline__ void cpa16(void* dst_smem, const void* src) {
    unsigned d = (unsigned)__cvta_generic_to_shared(dst_smem);
    asm volatile("cp.async.cg.shared.global [%0], [%1], 16;" :: "r"(d), "l"(src));
}
#define CP_COMMIT() asm volatile("cp.async.commit_group;")
#define CP_WAIT(n)  asm volatile("cp.async.wait_group %0;" :: "n"(n))

__device__ __forceinline__ void ldsm_x4(unsigned r[4], const void* p) {
    unsigned a = (unsigned)__cvta_generic_to_shared(p);
    asm volatile("ldmatrix.sync.aligned.m8n8.x4.shared.b16 {%0,%1,%2,%3}, [%4];"
                 : "=r"(r[0]), "=r"(r[1]), "=r"(r[2]), "=r"(r[3]) : "r"(a));
}
__device__ __forceinline__ void ldsm_x4_t(unsigned r[4], const void* p) {
    unsigned a = (unsigned)__cvta_generic_to_shared(p);
    asm volatile("ldmatrix.sync.aligned.m8n8.x4.trans.shared.b16 {%0,%1,%2,%3}, [%4];"
                 : "=r"(r[0]), "=r"(r[1]), "=r"(r[2]), "=r"(r[3]) : "r"(a));
}

// ================= kernel 1: projections via 3xTF32 MMA, fp16 outputs =================
#define WS_ST 132
__global__ void __launch_bounds__(256, 2) proj_kernel(
    const float* __restrict__ xq, const float* __restrict__ xk, const float* __restrict__ xv,
    const float* __restrict__ Wq, const float* __restrict__ bq,
    const float* __restrict__ Wk, const float* __restrict__ bk,
    const float* __restrict__ Wv, const float* __restrict__ bv)
{
    const int proj = blockIdx.z;
    const float* x; const float* W; const float* bias; __half* o;
    if (proj == 0)      { x = xq; W = Wq; bias = bq; o = g_q; }
    else if (proj == 1) { x = xk; W = Wk; bias = bk; o = g_k; }
    else                { x = xv; W = Wv; bias = bv; o = g_v; }

    const int row0 = blockIdx.x * 128;
    const int h0   = blockIdx.y * 128;

    __shared__ float xs_hi[128 * 20], xs_lo[128 * 20];
    __shared__ float ws_hi[16 * WS_ST], ws_lo[16 * WS_ST];

    const int tid = threadIdx.x;
    const int warp = tid >> 5, lane = tid & 31;
    const int wm = warp & 3, wn = warp >> 2;
    const int tg = lane & 3, gi = lane >> 2;

    float acc[2][8][4];
#pragma unroll
    for (int mi = 0; mi < 2; mi++)
#pragma unroll
        for (int ni = 0; ni < 8; ni++)
#pragma unroll
            for (int c = 0; c < 4; c++) acc[mi][ni][c] = 0.f;

    for (int kc = 0; kc < INDIM; kc += 16) {
#pragma unroll
        for (int i = 0; i < 2; i++) {
            int f4 = tid + i * 256;
            int r = f4 >> 2, c4 = (f4 & 3) * 4;
            float4 xv4 = *(const float4*)(x + (size_t)(row0 + r) * INDIM + kc + c4);
            float h0f, l0, h1, l1, h2, l2, h3, l3;
            split_tf32(xv4.x, h0f, l0); split_tf32(xv4.y, h1, l1);
            split_tf32(xv4.z, h2, l2); split_tf32(xv4.w, h3, l3);
            float* dh = xs_hi + r * 20 + c4;
            float* dl = xs_lo + r * 20 + c4;
            dh[0] = h0f; dh[1] = h1; dh[2] = h2; dh[3] = h3;
            dl[0] = l0;  dl[1] = l1; dl[2] = l2; dl[3] = l3;
        }
#pragma unroll
        for (int i = 0; i < 2; i++) {
            int f4 = tid + i * 256;
            int k = f4 >> 5, n4 = (f4 & 31) * 4;
            float4 wv4 = *(const float4*)(W + (size_t)(kc + k) * HID + h0 + n4);
            float h0f, l0, h1, l1, h2, l2, h3, l3;
            split_tf32(wv4.x, h0f, l0); split_tf32(wv4.y, h1, l1);
            split_tf32(wv4.z, h2, l2); split_tf32(wv4.w, h3, l3);
            *(float4*)(ws_hi + k * WS_ST + n4) = make_float4(h0f, h1, h2, h3);
            *(float4*)(ws_lo + k * WS_ST + n4) = make_float4(l0, l1, l2, l3);
        }
        __syncthreads();
#pragma unroll
        for (int ks = 0; ks < 16; ks += 8) {
            unsigned ah[2][4], al[2][4], bh[8][2], bl[8][2];
#pragma unroll
            for (int mi = 0; mi < 2; mi++) {
                int r = wm * 32 + mi * 16 + gi;
                ah[mi][0] = __float_as_uint(xs_hi[r * 20 + ks + tg]);
                ah[mi][1] = __float_as_uint(xs_hi[(r + 8) * 20 + ks + tg]);
                ah[mi][2] = __float_as_uint(xs_hi[r * 20 + ks + tg + 4]);
                ah[mi][3] = __float_as_uint(xs_hi[(r + 8) * 20 + ks + tg + 4]);
                al[mi][0] = __float_as_uint(xs_lo[r * 20 + ks + tg]);
                al[mi][1] = __float_as_uint(xs_lo[(r + 8) * 20 + ks + tg]);
                al[mi][2] = __float_as_uint(xs_lo[r * 20 + ks + tg + 4]);
                al[mi][3] = __float_as_uint(xs_lo[(r + 8) * 20 + ks + tg + 4]);
            }
#pragma unroll
            for (int ni = 0; ni < 8; ni++) {
                int n = wn * 64 + ni * 8 + gi;
                bh[ni][0] = __float_as_uint(ws_hi[(ks + tg) * WS_ST + n]);
                bh[ni][1] = __float_as_uint(ws_hi[(ks + tg + 4) * WS_ST + n]);
                bl[ni][0] = __float_as_uint(ws_lo[(ks + tg) * WS_ST + n]);
                bl[ni][1] = __float_as_uint(ws_lo[(ks + tg + 4) * WS_ST + n]);
            }
#pragma unroll
            for (int mi = 0; mi < 2; mi++)
#pragma unroll
                for (int ni = 0; ni < 8; ni++) {
                    mma_tf32(acc[mi][ni], ah[mi], bh[ni]);
                    mma_tf32(acc[mi][ni], ah[mi], bl[ni]);
                    mma_tf32(acc[mi][ni], al[mi], bh[ni]);
                }
        }
        __syncthreads();
    }
#pragma unroll
    for (int mi = 0; mi < 2; mi++) {
        int r0 = row0 + wm * 32 + mi * 16 + gi;
        int r1 = r0 + 8;
#pragma unroll
        for (int ni = 0; ni < 8; ni++) {
            int c = h0 + wn * 64 + ni * 8 + tg * 2;
            float2 bb = *(const float2*)(bias + c);
            *(__half2*)(o + (size_t)r0 * HID + c) =
                __float22half2_rn(make_float2(acc[mi][ni][0] + bb.x, acc[mi][ni][1] + bb.y));
            *(__half2*)(o + (size_t)r1 * HID + c) =
                __float22half2_rn(make_float2(acc[mi][ni][2] + bb.x, acc[mi][ni][3] + bb.y));
        }
    }
}

// ================= kernel 2: fused flash attention + LayerNorm =================
// grid (32 qt, 8 b), 256 threads (8 warps; wm=warp&1 -> 2x32 rows, wn=warp>>1 -> 4 col groups).
// Per kt tile of 64 keys: S = Q K^T (fp16 MMA) -> exp(masked) -> Ps smem -> O += Ps V.
#define QT 64
#define KT 64
#define QKV_ST 264          // halves; 528B = 33 granules -> conflict-free ldsm
#define PS_ST 72
#define Q_HALVES  (QT * QKV_ST)
#define KV_HALVES (KT * QKV_ST)
#define PS_HALVES (QT * PS_ST)
#define FUSED_SMEM_BYTES ((Q_HALVES + 2 * KV_HALVES + PS_HALVES) * 2 + (256 + 512) * 4)

__global__ void __launch_bounds__(256, 2) attn_kernel(const int* __restrict__ mask,
                                                      const float* __restrict__ gamma,
                                                      const float* __restrict__ beta,
                                                      float* __restrict__ out)
{
    const int qt = blockIdx.x, b = blockIdx.y;
    extern __shared__ __half smh[];
    __half* Qs = smh;
    __half* Kb = Qs + Q_HALVES;
    __half* Vb = Kb + KV_HALVES;
    __half* Ps = Vb + KV_HALVES;
    float* rsum_sm = (float*)(Ps + PS_HALVES);   // 4 x 64
    float* rstat   = rsum_sm + 256;              // 4 x 64 x 2

    const int tid = threadIdx.x;
    const int warp = tid >> 5, lane = tid & 31;
    const int wm = warp & 1, wn = warp >> 1;     // wm: rows, wn: 4 groups (S cols 16 / O cols 64)
    const int tg = lane & 3, gi = lane >> 2;
    const int l15 = lane & 15, lhi = (lane >> 4) << 3;

    const __half* Qg = g_q + ((size_t)b * SEQ + qt * QT) * HID;
    const __half* Kg = g_k + (size_t)b * SEQ * HID;
    const __half* Vg = g_v + (size_t)b * SEQ * HID;
    const int* Mg = mask + ((size_t)b * SEQ + qt * QT) * SEQ;

    float accO[2][8][4];
#pragma unroll
    for (int mi = 0; mi < 2; mi++)
#pragma unroll
        for (int ni = 0; ni < 8; ni++)
#pragma unroll
            for (int c = 0; c < 4; c++) accO[mi][ni][c] = 0.f;
    float rs[2][2] = {{0.f, 0.f}, {0.f, 0.f}};

    // prologue: Q + K0 (group A), V0 (group B)
#pragma unroll
    for (int i = 0; i < 8; i++) {
        int idx = tid + i * 256;                 // 0..2047: 64 rows x 32 granules
        int r = idx >> 5, g = idx & 31;
        cpa16(Qs + r * QKV_ST + g * 8, Qg + (size_t)r * HID + g * 8);
    }
#pragma unroll
    for (int i = 0; i < 8; i++) {
        int idx = tid + i * 256;
        int r = idx >> 5, g = idx & 31;
        cpa16(Kb + r * QKV_ST + g * 8, Kg + (size_t)r * HID + g * 8);
    }
    CP_COMMIT();
#pragma unroll
    for (int i = 0; i < 8; i++) {
        int idx = tid + i * 256;
        int r = idx >> 5, g = idx & 31;
        cpa16(Vb + r * QKV_ST + g * 8, Vg + (size_t)r * HID + g * 8);
    }
    CP_COMMIT();

    const int NKT2 = SEQ / KT;   // 32
    for (int kt = 0; kt < NKT2; kt++) {
        // mask prefetch into registers (in flight during S-MMA)
        int2 mreg[8];
#pragma unroll
        for (int mi = 0; mi < 2; mi++)
#pragma unroll
            for (int ni = 0; ni < 2; ni++) {
                int r0 = wm * 32 + mi * 16 + gi;
                int c0 = wn * 16 + ni * 8 + tg * 2;
                mreg[(mi * 2 + ni) * 2 + 0] = *(const int2*)(Mg + (size_t)r0 * SEQ + kt * KT + c0);
                mreg[(mi * 2 + ni) * 2 + 1] = *(const int2*)(Mg + (size_t)(r0 + 8) * SEQ + kt * KT + c0);
            }

        CP_WAIT(1);                 // Q + K[kt] ready (V[kt] may still be pending)
        __syncthreads();

        // ---- S = Q K^T over K=256 ----
        float accS[2][2][4];
#pragma unroll
        for (int mi = 0; mi < 2; mi++)
#pragma unroll
            for (int ni = 0; ni < 2; ni++)
#pragma unroll
                for (int c = 0; c < 4; c++) accS[mi][ni][c] = 0.f;
#pragma unroll
        for (int ks = 0; ks < HID; ks += 16) {
            unsigned a[2][4], bb[4];
            ldsm_x4(a[0], Qs + (wm * 32 + l15) * QKV_ST + ks + lhi);
            ldsm_x4(a[1], Qs + (wm * 32 + 16 + l15) * QKV_ST + ks + lhi);
            ldsm_x4(bb,   Kb + (wn * 16 + l15) * QKV_ST + ks + lhi);
            mma_f16(accS[0][0], a[0], bb[0], bb[2]);
            mma_f16(accS[0][1], a[0], bb[1], bb[3]);
            mma_f16(accS[1][0], a[1], bb[0], bb[2]);
            mma_f16(accS[1][1], a[1], bb[1], bb[3]);
        }

        // ---- epilogue: mask, exp, rowsum, Ps ----
        const float scale = 0.0625f;
#pragma unroll
        for (int mi = 0; mi < 2; mi++) {
            int r0 = wm * 32 + mi * 16 + gi;
            int r1 = r0 + 8;
#pragma unroll
            for (int ni = 0; ni < 2; ni++) {
                int c0 = wn * 16 + ni * 8 + tg * 2;
                int2 m0 = mreg[(mi * 2 + ni) * 2 + 0];
                int2 m1 = mreg[(mi * 2 + ni) * 2 + 1];
                float p00 = m0.x ? __expf(accS[mi][ni][0] * scale) : 0.f;
                float p01 = m0.y ? __expf(accS[mi][ni][1] * scale) : 0.f;
                float p10 = m1.x ? __expf(accS[mi][ni][2] * scale) : 0.f;
                float p11 = m1.y ? __expf(accS[mi][ni][3] * scale) : 0.f;
                rs[mi][0] += p00 + p01;
                rs[mi][1] += p10 + p11;
                *(__half2*)(Ps + r0 * PS_ST + c0) = __float22half2_rn(make_float2(p00, p01));
                *(__half2*)(Ps + r1 * PS_ST + c0) = __float22half2_rn(make_float2(p10, p11));
            }
        }
        __syncthreads();             // Ps ready; Kb free

        if (kt + 1 < NKT2) {
#pragma unroll
            for (int i = 0; i < 8; i++) {
                int idx = tid + i * 256;
                int r = idx >> 5, g = idx & 31;
                cpa16(Kb + r * QKV_ST + g * 8, Kg + (size_t)((kt + 1) * KT + r) * HID + g * 8);
            }
            CP_COMMIT();
            CP_WAIT(1);              // V[kt] done, K[kt+1] in flight
        } else {
            CP_WAIT(0);
        }
        __syncthreads();             // Vb visible

        // ---- O += Ps V ----
#pragma unroll
        for (int ks = 0; ks < KT; ks += 16) {
            unsigned a[2][4], bb[4][4];
#pragma unroll
            for (int mi = 0; mi < 2; mi++)
                ldsm_x4(a[mi], Ps + (wm * 32 + mi * 16 + l15) * PS_ST + ks + lhi);
#pragma unroll
            for (int nj = 0; nj < 4; nj++)
                ldsm_x4_t(bb[nj], Vb + (size_t)(ks + l15) * QKV_ST + wn * 64 + nj * 16 + lhi);
#pragma unroll
            for (int mi = 0; mi < 2; mi++)
#pragma unroll
                for (int nj = 0; nj < 4; nj++) {
                    mma_f16(accO[mi][nj * 2],     a[mi], bb[nj][0], bb[nj][1]);
                    mma_f16(accO[mi][nj * 2 + 1], a[mi], bb[nj][2], bb[nj][3]);
                }
        }
        __syncthreads();             // Vb free

        if (kt + 1 < NKT2) {
#pragma unroll
            for (int i = 0; i < 8; i++) {
                int idx = tid + i * 256;
                int r = idx >> 5, g = idx & 31;
                cpa16(Vb + r * QKV_ST + g * 8, Vg + (size_t)((kt + 1) * KT + r) * HID + g * 8);
            }
            CP_COMMIT();
        }
    }

    // ---- rowsum cross-warp reduction ----
#pragma unroll
    for (int mi = 0; mi < 2; mi++) {
#pragma unroll
        for (int h = 0; h < 2; h++) {
            float v = rs[mi][h];
            v += __shfl_xor_sync(0xffffffffu, v, 1);
            v += __shfl_xor_sync(0xffffffffu, v, 2);
            rs[mi][h] = v;
        }
        if (tg == 0) {
            int rl = wm * 32 + mi * 16 + gi;
            rsum_sm[wn * 64 + rl]     = rs[mi][0];
            rsum_sm[wn * 64 + rl + 8] = rs[mi][1];
        }
    }
    __syncthreads();

    // ---- normalize + per-row sum/sumsq ----
#pragma unroll
    for (int mi = 0; mi < 2; mi++) {
        int rl0 = wm * 32 + mi * 16 + gi;
        int rl1 = rl0 + 8;
        float t0 = rsum_sm[rl0] + rsum_sm[64 + rl0] + rsum_sm[128 + rl0] + rsum_sm[192 + rl0];
        float t1 = rsum_sm[rl1] + rsum_sm[64 + rl1] + rsum_sm[128 + rl1] + rsum_sm[192 + rl1];
        float i0 = 1.f / t0, i1 = 1.f / t1;
        float s0 = 0.f, s1 = 0.f, q0 = 0.f, q1 = 0.f;
#pragma unroll
        for (int ni = 0; ni < 8; ni++) {
            float v00 = accO[mi][ni][0] * i0; accO[mi][ni][0] = v00;
            float v01 = accO[mi][ni][1] * i0; accO[mi][ni][1] = v01;
            float v10 = accO[mi][ni][2] * i1; accO[mi][ni][2] = v10;
            float v11 = accO[mi][ni][3] * i1; accO[mi][ni][3] = v11;
            s0 += v00 + v01; s1 += v10 + v11;
            q0 += v00 * v00 + v01 * v01;
            q1 += v10 * v10 + v11 * v11;
        }
        s0 += __shfl_xor_sync(0xffffffffu, s0, 1); s0 += __shfl_xor_sync(0xffffffffu, s0, 2);
        s1 += __shfl_xor_sync(0xffffffffu, s1, 1); s1 += __shfl_xor_sync(0xffffffffu, s1, 2);
        q0 += __shfl_xor_sync(0xffffffffu, q0, 1); q0 += __shfl_xor_sync(0xffffffffu, q0, 2);
        q1 += __shfl_xor_sync(0xffffffffu, q1, 1); q1 += __shfl_xor_sync(0xffffffffu, q1, 2);
        if (tg == 0) {
            rstat[wn * 128 + rl0 * 2]     = s0;
            rstat[wn * 128 + rl0 * 2 + 1] = q0;
            rstat[wn * 128 + rl1 * 2]     = s1;
            rstat[wn * 128 + rl1 * 2 + 1] = q1;
        }
    }
    __syncthreads();

    // ---- LayerNorm + write ----
#pragma unroll
    for (int mi = 0; mi < 2; mi++) {
        int rl0 = wm * 32 + mi * 16 + gi;
        int rl1 = rl0 + 8;
        float sum0 = rstat[rl0*2] + rstat[128 + rl0*2] + rstat[256 + rl0*2] + rstat[384 + rl0*2];
        float sq0  = rstat[rl0*2+1] + rstat[128 + rl0*2+1] + rstat[256 + rl0*2+1] + rstat[384 + rl0*2+1];
        float sum1 = rstat[rl1*2] + rstat[128 + rl1*2] + rstat[256 + rl1*2] + rstat[384 + rl1*2];
        float sq1  = rstat[rl1*2+1] + rstat[128 + rl1*2+1] + rstat[256 + rl1*2+1] + rstat[384 + rl1*2+1];
        float mu0 = sum0 * (1.f / HID);
        float mu1 = sum1 * (1.f / HID);
        float var0 = sq0 * (1.f / HID) - mu0 * mu0;
        float var1 = sq1 * (1.f / HID) - mu1 * mu1;
        float rstd0 = rsqrtf(var0 + 1e-6f);
        float rstd1 = rsqrtf(var1 + 1e-6f);
        size_t orow0 = ((size_t)b * SEQ + qt * QT + rl0) * HID;
        size_t orow1 = ((size_t)b * SEQ + qt * QT + rl1) * HID;
#pragma unroll
        for (int ni = 0; ni < 8; ni++) {
            int c0 = wn * 64 + ni * 8 + tg * 2;
            float2 gm = *(const float2*)(gamma + c0);
            float2 bt = *(const float2*)(beta + c0);
            float2 o0, o1;
            o0.x = (accO[mi][ni][0] - mu0) * rstd0 * gm.x + bt.x;
            o0.y = (accO[mi][ni][1] - mu0) * rstd0 * gm.y + bt.y;
            o1.x = (accO[mi][ni][2] - mu1) * rstd1 * gm.x + bt.x;
            o1.y = (accO[mi][ni][3] - mu1) * rstd1 * gm.y + bt.y;
            *(float2*)(out + orow0 + c0) = o0;
            *(float2*)(out + orow1 + c0) = o1;
        }
    }
}

// ---------------- launch ----------------
extern "C" void kernel_launch(void* const* d_in, const int* in_sizes, int n_in,
                              void* d_out, int out_size)
{
    const float* q     = (const float*)d_in[0];
    const float* k     = (const float*)d_in[1];
    const float* v     = (const float*)d_in[2];
    const int*   mask  = (const int*)  d_in[3];
    const float* Wq    = (const float*)d_in[4];
    const float* bq    = (const float*)d_in[5];
    const float* Wk    = (const float*)d_in[6];
    const float* bk    = (const float*)d_in[7];
    const float* Wv    = (const float*)d_in[8];
    const float* bv    = (const float*)d_in[9];
    const float* gamma = (const float*)d_in[10];
    const float* beta  = (const float*)d_in[11];
    float* out = (float*)d_out;

    static int inited = 0;
    if (!inited) {
        cudaFuncSetAttribute(attn_kernel, cudaFuncAttributeMaxDynamicSharedMemorySize, FUSED_SMEM_BYTES);
        inited = 1;
    }

    dim3 gp(BATCH * SEQ / 128, HID / 128, 3);
    proj_kernel<<<gp, 256>>>(q, k, v, Wq, bq, Wk, bk, Wv, bv);

    dim3 ga(SEQ / QT, BATCH);
    attn_kernel<<<ga, 256, FUSED_SMEM_BYTES>>>(mask, gamma, beta, out);
}